// round 7
// baseline (speedup 1.0000x reference)
#include <cuda_runtime.h>
#include <math.h>

#define NX    4096
#define NEQ   768
#define MU    0.1
#define SIG   0.1
#define ITERS 40
#define NBLK  132
#define NTHR  256
#define SMEM_DBL 8320          // 66560 bytes dynamic shared

// ---------------- device-global state ----------------
__device__ double g_A[(size_t)NEQ * NX];
__device__ double g_AT[(size_t)NX * NEQ];
__device__ double g_q[NX];
__device__ double g_b[NEQ];
__device__ double g_z[NX];
__device__ double g_lam[NX];
__device__ double g_nu[NEQ];
__device__ double g_t[NX];
__device__ double g_rc[NX];
__device__ double g_Dinv[NX];
__device__ double g_rtil[NX];
__device__ double g_w[NX];
__device__ double g_dnu[NEQ];
__device__ double g_rhs[NEQ];
__device__ double g_ADA[NEQ * NEQ];
__device__ double g_dz[NX];
__device__ double g_dlam[NX];
__device__ double g_part[16];
__device__ double g_pmin[16];
__device__ int    g_is64;
__device__ unsigned g_count;

__global__ void k_reset() { g_count = 0u; }

// software grid barrier: monotonic counter, one arrival per block
__device__ __forceinline__ void gsync(unsigned &tgt) {
    __syncthreads();
    __threadfence();                       // release
    if (threadIdx.x == 0) {
        atomicAdd(&g_count, 1u);
        tgt += NBLK;
        while (atomicAdd(&g_count, 0u) < tgt) __nanosleep(64);
    }
    __syncthreads();
    __threadfence();                       // acquire
}

// deterministic block reductions (fixed tree + fixed serial order)
__device__ __forceinline__ void blk_sum_to(double v, double* s_red, int tid, double* dst) {
#pragma unroll
    for (int off = 16; off; off >>= 1) v += __shfl_down_sync(0xffffffffu, v, off);
    if ((tid & 31) == 0) s_red[tid >> 5] = v;
    __syncthreads();
    if (tid == 0) { double r = 0; for (int w = 0; w < 8; w++) r += s_red[w]; *dst = r; }
    __syncthreads();
}
__device__ __forceinline__ void blk_min_to(double v, double* s_red, int tid, double* dst) {
#pragma unroll
    for (int off = 16; off; off >>= 1) v = fmin(v, __shfl_down_sync(0xffffffffu, v, off));
    if ((tid & 31) == 0) s_red[tid >> 5] = v;
    __syncthreads();
    if (tid == 0) { double r = s_red[0]; for (int w = 1; w < 8; w++) r = fmin(r, s_red[w]); *dst = r; }
    __syncthreads();
}

__device__ __forceinline__ void tri_map(int t, int &bi, int &bj) {
    int b = 0;
    while ((b + 1) * (b + 2) / 2 <= t) b++;
    bi = b; bj = t - b * (b + 1) / 2;
}

// A @ w  (mode 0 -> g_b ; mode 1 -> g_rhs = A@w - b)
__device__ __forceinline__ void amv_phase(double* sv, int mode, int bid, int tid, int warp, int lane) {
    for (int i = tid; i < NX; i += NTHR) sv[i] = g_w[i];
    __syncthreads();
    int row = bid * 8 + warp;
    if (row < NEQ) {
        const double* ar = g_A + (size_t)row * NX;
        double s = 0.0;
        for (int k = lane; k < NX; k += 32) s += ar[k] * sv[k];
#pragma unroll
        for (int off = 16; off; off >>= 1) s += __shfl_down_sync(0xffffffffu, s, off);
        if (lane == 0) { if (mode == 0) g_b[row] = s; else g_rhs[row] = s - g_b[row]; }
    }
    __syncthreads();
}

// g_t = A^T @ (mode ? dnu : nu)
__device__ __forceinline__ void atmv_phase(double* sx, int mode, int bid, int tid, int warp, int lane) {
    const double* x = mode ? g_dnu : g_nu;
    for (int i = tid; i < NEQ; i += NTHR) sx[i] = x[i];
    __syncthreads();
    for (int j = bid * 8 + warp; j < NX; j += NBLK * 8) {
        const double* ar = g_AT + (size_t)j * NEQ;
        double s = 0.0;
        for (int e = lane; e < NEQ; e += 32) s += ar[e] * sx[e];
#pragma unroll
        for (int off = 16; off; off >>= 1) s += __shfl_down_sync(0xffffffffu, s, off);
        if (lane == 0) g_t[j] = s;
    }
    __syncthreads();
}

__global__ void __launch_bounds__(NTHR, 1)
k_main(const float* __restrict__ puz, const void* __restrict__ Araw,
       const float* __restrict__ logz, float* __restrict__ out) {
    extern __shared__ double sh[];
    __shared__ double s_red[32];
    __shared__ double s_val;
    __shared__ int s_cnt;
    const int tid = threadIdx.x, bid = blockIdx.x;
    const int warp = tid >> 5, lane = tid & 31;
    unsigned tgt = 0;

    // ---- phase: dtype detect (block 0 reads first 16KB only: safe either way)
    if (bid == 0) {
        if (tid == 0) s_cnt = 0;
        __syncthreads();
        int c = 0;
        const unsigned* W = (const unsigned*)Araw;
        for (int i = tid; i < 4096; i += NTHR) {
            float v = __uint_as_float(W[i]);
            if (v >= 1.0f && v < 4.0f) c++;   // fp64 high words land here; fp32 U[0,1) never
        }
        atomicAdd(&s_cnt, c);
        __syncthreads();
        if (tid == 0) g_is64 = (s_cnt > 64) ? 1 : 0;
    }
    gsync(tgt);

    // ---- phase: widen A + init state
    {
        int is64 = g_is64;
        const double* Ad = (const double*)Araw;
        const float*  Af = (const float*)Araw;
        for (size_t i = (size_t)bid * NTHR + tid; i < (size_t)NEQ * NX; i += (size_t)NBLK * NTHR)
            g_A[i] = is64 ? Ad[i] : (double)Af[i];
        int i = bid * NTHR + tid;
        if (i < NX) {
            g_q[i] = -(double)puz[i];
            g_z[i] = 1.0; g_lam[i] = 1.0;
            g_w[i] = exp((double)logz[i]);
        }
        if (i < NEQ) g_nu[i] = 0.0;
    }
    gsync(tgt);

    // ---- phase: transpose A -> g_AT (32x32 tiles)
    {
        int tx = tid & 31, ty = tid >> 5;
        for (int t = bid; t < (NX / 32) * (NEQ / 32); t += NBLK) {
            int j0 = (t % (NX / 32)) * 32, e0 = (t / (NX / 32)) * 32;
#pragma unroll
            for (int m = 0; m < 4; m++) {
                int e = e0 + ty + 8 * m;
                sh[(ty + 8 * m) * 33 + tx] = g_A[(size_t)e * NX + j0 + tx];
            }
            __syncthreads();
#pragma unroll
            for (int m = 0; m < 4; m++) {
                int j = j0 + ty + 8 * m;
                g_AT[(size_t)j * NEQ + e0 + tx] = sh[tx * 33 + ty + 8 * m];
            }
            __syncthreads();
        }
    }
    gsync(tgt);

    // ---- phase: b = A @ exp(log_z0)
    amv_phase(sh, 0, bid, tid, warp, lane);
    gsync(tgt);

    // =================== IPM loop ===================
    for (int it = 0; it < ITERS; it++) {
        // t = A^T nu
        atmv_phase(sh, 0, bid, tid, warp, lane);
        gsync(tgt);

        // pre A: partial dot(z,lam)
        if (bid < 16) {
            int i = bid * NTHR + tid;
            blk_sum_to(g_z[i] * g_lam[i], s_red, tid, &s_val);
            if (tid == 0) g_part[bid] = s_val;
        }
        gsync(tgt);

        // pre B: gap + residual vectors
        if (bid < 16) {
            double gap = 0;
#pragma unroll
            for (int j = 0; j < 16; j++) gap += g_part[j];
            gap /= (double)NX;
            int i = bid * NTHR + tid;
            double z = g_z[i], la = g_lam[i];
            double rd = MU * z + g_q[i] - la + g_t[i];
            double rc = z * la - SIG * gap;
            double Di = 1.0 / (MU + la / z);
            double rt = -rd - rc / z;
            g_rc[i] = rc; g_Dinv[i] = Di; g_rtil[i] = rt;
            g_w[i] = rt * Di + z;
        }
        gsync(tgt);

        // rhs = A@w - b
        amv_phase(sh, 1, bid, tid, warp, lane);
        gsync(tgt);

        // ADA lower-tri = A diag(Dinv) A^T  (300 32x32 tiles)
        {
            double* As = sh;           // [32][33]
            double* Bs = sh + 1056;    // [32][33]
            int tx = tid & 31, ty = tid >> 5;
            for (int t = bid; t < 300; t += NBLK) {
                int bi, bj; tri_map(t, bi, bj);
                int row0 = bi * 32, col0 = bj * 32;
                double a0 = 0, a1 = 0, a2 = 0, a3 = 0;
                for (int k0 = 0; k0 < NX; k0 += 32) {
                    double dv = g_Dinv[k0 + tx];
#pragma unroll
                    for (int m = 0; m < 4; m++) {
                        int i = ty + 8 * m;
                        As[tx * 33 + i] = g_A[(size_t)(row0 + i) * NX + k0 + tx];
                        Bs[tx * 33 + i] = g_A[(size_t)(col0 + i) * NX + k0 + tx] * dv;
                    }
                    __syncthreads();
#pragma unroll
                    for (int k = 0; k < 32; k++) {
                        double bv = Bs[k * 33 + tx];
                        a0 += As[k * 33 + ty]      * bv;
                        a1 += As[k * 33 + ty + 8]  * bv;
                        a2 += As[k * 33 + ty + 16] * bv;
                        a3 += As[k * 33 + ty + 24] * bv;
                    }
                    __syncthreads();
                }
                size_t base = (size_t)row0 * NEQ + col0 + tx;
                g_ADA[base + (size_t)(ty)      * NEQ] = a0;
                g_ADA[base + (size_t)(ty + 8)  * NEQ] = a1;
                g_ADA[base + (size_t)(ty + 16) * NEQ] = a2;
                g_ADA[base + (size_t)(ty + 24) * NEQ] = a3;
            }
        }
        gsync(tgt);

        // ---- Cholesky: 12 panels of 64 ----
        for (int p = 0; p < 12; p++) {
            int o = p * 64, rem = NEQ - o - 64;
            // potrf (block 0)
            if (bid == 0) {
                double* S = sh;  // [64][65]
                int c = tid & 63, r0 = tid >> 6;
#pragma unroll
                for (int m = 0; m < 16; m++) { int r = r0 + 4 * m; S[r * 65 + c] = g_ADA[(size_t)(o + r) * NEQ + o + c]; }
                __syncthreads();
                int l = tid >> 2, cc = tid & 3;
                for (int j = 0; j < 64; j++) {
                    if (tid == 0) S[j * 65 + j] = sqrt(fmax(S[j * 65 + j], 1e-300));
                    __syncthreads();
                    if (tid > j && tid < 64) S[tid * 65 + j] /= S[j * 65 + j];
                    __syncthreads();
                    if (l > j) {
                        double ljj = S[l * 65 + j];
                        for (int k = j + 1 + cc; k <= l; k += 4) S[l * 65 + k] -= ljj * S[k * 65 + j];
                    }
                    __syncthreads();
                }
#pragma unroll
                for (int m = 0; m < 16; m++) { int r = r0 + 4 * m; g_ADA[(size_t)(o + r) * NEQ + o + c] = S[r * 65 + c]; }
            }
            gsync(tgt);

            // trsm: L21 = A21 * L11^{-T}, 64-row chunks per block (smem-based)
            if (rem > 0 && bid < rem / 64) {
                double* L = sh;          // [64][65]
                double* X = sh + 4160;   // [64][65]
                int base = o + 64 + bid * 64;
                for (int i = tid; i < 4096; i += NTHR) {
                    int r = i >> 6, c = i & 63;
                    L[r * 65 + c] = g_ADA[(size_t)(o + r) * NEQ + o + c];
                    X[r * 65 + c] = g_ADA[(size_t)(base + r) * NEQ + o + c];
                }
                __syncthreads();
                if (tid < 64) {
                    int r = tid;
                    for (int j = 0; j < 64; j++) {
                        double s = X[r * 65 + j];
                        for (int k = 0; k < j; k++) s -= X[r * 65 + k] * L[j * 65 + k];
                        X[r * 65 + j] = s / L[j * 65 + j];
                    }
                }
                __syncthreads();
                for (int i = tid; i < 4096; i += NTHR) {
                    int r = i >> 6, c = i & 63;
                    g_ADA[(size_t)(base + r) * NEQ + o + c] = X[r * 65 + c];
                }
            }
            gsync(tgt);

            // syrk: trailing C -= L21 L21^T over lower 32x32 tiles, K=64
            if (rem > 0) {
                int nb = rem / 32, nt = nb * (nb + 1) / 2;
                double* As = sh;           // [64][33]
                double* Bs = sh + 2112;    // [64][33]
                int tx = tid & 31, ty = tid >> 5;
                int kk = tid & 63, ii = tid >> 6;
                int o2 = o + 64;
                for (int t = bid; t < nt; t += NBLK) {
                    int bi, bj; tri_map(t, bi, bj);
                    int r0 = o2 + bi * 32, c0 = o2 + bj * 32;
#pragma unroll
                    for (int m = 0; m < 8; m++) {
                        int i = ii + 4 * m;
                        As[kk * 33 + i] = g_ADA[(size_t)(r0 + i) * NEQ + o + kk];
                        Bs[kk * 33 + i] = g_ADA[(size_t)(c0 + i) * NEQ + o + kk];
                    }
                    __syncthreads();
                    double a0 = 0, a1 = 0, a2 = 0, a3 = 0;
#pragma unroll
                    for (int k = 0; k < 64; k++) {
                        double bv = Bs[k * 33 + tx];
                        a0 += As[k * 33 + ty]      * bv;
                        a1 += As[k * 33 + ty + 8]  * bv;
                        a2 += As[k * 33 + ty + 16] * bv;
                        a3 += As[k * 33 + ty + 24] * bv;
                    }
                    size_t basew = (size_t)r0 * NEQ + c0 + tx;
                    g_ADA[basew + (size_t)(ty)      * NEQ] -= a0;
                    g_ADA[basew + (size_t)(ty + 8)  * NEQ] -= a1;
                    g_ADA[basew + (size_t)(ty + 16) * NEQ] -= a2;
                    g_ADA[basew + (size_t)(ty + 24) * NEQ] -= a3;
                    __syncthreads();
                }
            }
            gsync(tgt);
        }

        // ---- triangular solves (block 0, 256 threads) ----
        if (bid == 0) {
            double* S = sh;          // [64][65]
            double* y = sh + 4160;   // [768]
            for (int i = tid; i < NEQ; i += NTHR) y[i] = g_rhs[i];
            __syncthreads();
            // forward
            for (int p = 0; p < 12; p++) {
                int o = p * 64;
                for (int i = tid; i < 4096; i += NTHR) {
                    int r = i >> 6, c = i & 63;
                    S[r * 65 + c] = g_ADA[(size_t)(o + r) * NEQ + o + c];
                }
                __syncthreads();
                for (int j = 0; j < 64; j++) {
                    if (tid == 0) y[o + j] /= S[j * 65 + j];
                    __syncthreads();
                    double yj = y[o + j];
                    if (tid > j && tid < 64) y[o + tid] -= S[tid * 65 + j] * yj;
                    __syncthreads();
                }
                for (int r = o + 64 + warp; r < NEQ; r += 8) {
                    double s = 0.0;
#pragma unroll
                    for (int k = lane; k < 64; k += 32) s += g_ADA[(size_t)r * NEQ + o + k] * y[o + k];
#pragma unroll
                    for (int off = 16; off; off >>= 1) s += __shfl_down_sync(0xffffffffu, s, off);
                    if (lane == 0) y[r] -= s;
                }
                __syncthreads();
            }
            // backward
            for (int p = 11; p >= 0; p--) {
                int o = p * 64;
                for (int i = tid; i < 4096; i += NTHR) {
                    int r = i >> 6, c = i & 63;
                    S[r * 65 + c] = g_ADA[(size_t)(o + r) * NEQ + o + c];
                }
                __syncthreads();
                for (int j = 63; j >= 0; j--) {
                    if (tid == 0) y[o + j] /= S[j * 65 + j];
                    __syncthreads();
                    double xj = y[o + j];
                    if (tid < j) y[o + tid] -= S[j * 65 + tid] * xj;
                    __syncthreads();
                }
                for (int i = tid; i < o; i += NTHR) {
                    double s = 0.0;
#pragma unroll 8
                    for (int jj = 0; jj < 64; jj++) s += g_ADA[(size_t)(o + jj) * NEQ + i] * y[o + jj];
                    y[i] -= s;
                }
                __syncthreads();
            }
            for (int i = tid; i < NEQ; i += NTHR) g_dnu[i] = y[i];
        }
        gsync(tgt);

        // t = A^T dnu
        atmv_phase(sh, 1, bid, tid, warp, lane);
        gsync(tgt);

        // step A: dz, dlam, partial min
        if (bid < 16) {
            int i = bid * NTHR + tid;
            double rt = g_rtil[i], t2 = g_t[i], Di = g_Dinv[i];
            double rc = g_rc[i], la = g_lam[i], zz = g_z[i];
            double dz = (rt - t2) * Di;
            double dl = (-rc - la * dz) / zz;
            g_dz[i] = dz; g_dlam[i] = dl;
            double mn = INFINITY;
            if (dz < 0.0) mn = fmin(mn, -zz / dz);
            if (dl < 0.0) mn = fmin(mn, -la / dl);
            blk_min_to(mn, s_red, tid, &s_val);
            if (tid == 0) g_pmin[bid] = s_val;
        }
        gsync(tgt);

        // step B: alpha + update z, lam, nu
        {
            double a = INFINITY;
#pragma unroll
            for (int j = 0; j < 16; j++) a = fmin(a, g_pmin[j]);
            a = fmin(1.0, 0.99 * a);
            if (bid < 16) {
                int i = bid * NTHR + tid;
                g_z[i]   += a * g_dz[i];
                g_lam[i] += a * g_dlam[i];
            } else if (bid < 19) {
                int i = (bid - 16) * NTHR + tid;
                if (i < NEQ) g_nu[i] += a * g_dnu[i];
            }
        }
        gsync(tgt);
    }

    // ---- output ----
    if (bid < 16) {
        int i = bid * NTHR + tid;
        out[i] = (float)g_z[i];
    }
}

// ---------------- host launcher (2 graph nodes) ----------------
extern "C" void kernel_launch(void* const* d_in, const int* in_sizes, int n_in,
                              void* d_out, int out_size) {
    const float* puz  = (const float*)d_in[0];
    const void*  Araw = d_in[1];
    const float* logz = (const float*)d_in[2];
    float* out = (float*)d_out;

    static int attr_set = 0;
    if (!attr_set) {
        cudaFuncSetAttribute(k_main, cudaFuncAttributeMaxDynamicSharedMemorySize,
                             SMEM_DBL * (int)sizeof(double));
        attr_set = 1;
    }

    k_reset<<<1, 1>>>();
    k_main<<<NBLK, NTHR, SMEM_DBL * sizeof(double)>>>(puz, Araw, logz, out);
}

// round 8
// speedup vs baseline: 2.4701x; 2.4701x over previous
#include <cuda_runtime.h>
#include <math.h>

#define NX    4096
#define NEQ   768
#define MU    0.1
#define SIG   0.1
#define ITERS 40
#define NBLK  132
#define NTHR  256
#define SMEM_DBL 8320          // 66560 bytes dynamic shared

// ---------------- device-global state ----------------
__device__ double g_A[(size_t)NEQ * NX];
__device__ double g_AT[(size_t)NX * NEQ];
__device__ float  g_Ah[(size_t)NEQ * NX];   // A split hi
__device__ float  g_Al[(size_t)NEQ * NX];   // A split lo
__device__ float  g_Bh[(size_t)NEQ * NX];   // (A * Dinv) split hi, per iteration
__device__ float  g_Bl[(size_t)NEQ * NX];   // (A * Dinv) split lo
__device__ double g_q[NX];
__device__ double g_b[NEQ];
__device__ double g_z[NX];
__device__ double g_lam[NX];
__device__ double g_nu[NEQ];
__device__ double g_t[NX];
__device__ double g_rc[NX];
__device__ double g_Dinv[NX];
__device__ double g_rtil[NX];
__device__ double g_w[NX];
__device__ double g_dnu[NEQ];
__device__ double g_rhs[NEQ];
__device__ double g_ADA[NEQ * NEQ];
__device__ double g_dz[NX];
__device__ double g_dlam[NX];
__device__ double g_part[16];
__device__ double g_pmin[16];
__device__ int    g_is64;
__device__ unsigned g_count;

__global__ void k_reset() { g_count = 0u; }

// software grid barrier: monotonic counter, one arrival per block
__device__ __forceinline__ void gsync(unsigned &tgt) {
    __syncthreads();
    __threadfence();                       // release
    if (threadIdx.x == 0) {
        atomicAdd(&g_count, 1u);
        tgt += NBLK;
        while (atomicAdd(&g_count, 0u) < tgt) __nanosleep(64);
    }
    __syncthreads();
    __threadfence();                       // acquire
}

// deterministic block reductions
__device__ __forceinline__ void blk_sum_to(double v, double* s_red, int tid, double* dst) {
#pragma unroll
    for (int off = 16; off; off >>= 1) v += __shfl_down_sync(0xffffffffu, v, off);
    if ((tid & 31) == 0) s_red[tid >> 5] = v;
    __syncthreads();
    if (tid == 0) { double r = 0; for (int w = 0; w < 8; w++) r += s_red[w]; *dst = r; }
    __syncthreads();
}
__device__ __forceinline__ void blk_min_to(double v, double* s_red, int tid, double* dst) {
#pragma unroll
    for (int off = 16; off; off >>= 1) v = fmin(v, __shfl_down_sync(0xffffffffu, v, off));
    if ((tid & 31) == 0) s_red[tid >> 5] = v;
    __syncthreads();
    if (tid == 0) { double r = s_red[0]; for (int w = 1; w < 8; w++) r = fmin(r, s_red[w]); *dst = r; }
    __syncthreads();
}

__device__ __forceinline__ void tri_map(int t, int &bi, int &bj) {
    int b = 0;
    while ((b + 1) * (b + 2) / 2 <= t) b++;
    bi = b; bj = t - b * (b + 1) / 2;
}

// df64 MAC, fast2sum accumulation (terms predominantly same-magnitude/positive)
__device__ __forceinline__ void df_mac_fast(float ah, float al, float bh, float bl,
                                            float &Sh, float &Sl) {
    float p = __fmul_rn(ah, bh);
    float e = __fmaf_rn(ah, bh, -p);
    e = __fmaf_rn(ah, bl, e);
    e = __fmaf_rn(al, bh, e);
    float t = __fadd_rn(Sh, p);
    float e2 = __fadd_rn(__fsub_rn(Sh, t), p);
    Sh = t;
    Sl = __fadd_rn(Sl, __fadd_rn(e, e2));
}

// df64 MAC, full Knuth 2Sum (mixed-sign terms)
__device__ __forceinline__ void df_mac_knuth(float ah, float al, float bh, float bl,
                                             float &Sh, float &Sl) {
    float p = __fmul_rn(ah, bh);
    float e = __fmaf_rn(ah, bh, -p);
    e = __fmaf_rn(ah, bl, e);
    e = __fmaf_rn(al, bh, e);
    float s = __fadd_rn(Sh, p);
    float bb = __fsub_rn(s, Sh);
    float err = __fadd_rn(__fsub_rn(Sh, __fsub_rn(s, bb)), __fsub_rn(p, bb));
    Sh = s;
    Sl = __fadd_rn(Sl, __fadd_rn(e, err));
}

// A @ w  (mode 0 -> g_b ; mode 1 -> g_rhs = A@w - b)
__device__ __forceinline__ void amv_phase(double* sv, int mode, int bid, int tid, int warp, int lane) {
    for (int i = tid; i < NX; i += NTHR) sv[i] = g_w[i];
    __syncthreads();
    int row = bid * 8 + warp;
    if (row < NEQ) {
        const double* ar = g_A + (size_t)row * NX;
        double s = 0.0;
        for (int k = lane; k < NX; k += 32) s += ar[k] * sv[k];
#pragma unroll
        for (int off = 16; off; off >>= 1) s += __shfl_down_sync(0xffffffffu, s, off);
        if (lane == 0) { if (mode == 0) g_b[row] = s; else g_rhs[row] = s - g_b[row]; }
    }
    __syncthreads();
}

// g_t = A^T @ (mode ? dnu : nu)
__device__ __forceinline__ void atmv_phase(double* sx, int mode, int bid, int tid, int warp, int lane) {
    const double* x = mode ? g_dnu : g_nu;
    for (int i = tid; i < NEQ; i += NTHR) sx[i] = x[i];
    __syncthreads();
    for (int j = bid * 8 + warp; j < NX; j += NBLK * 8) {
        const double* ar = g_AT + (size_t)j * NEQ;
        double s = 0.0;
        for (int e = lane; e < NEQ; e += 32) s += ar[e] * sx[e];
#pragma unroll
        for (int off = 16; off; off >>= 1) s += __shfl_down_sync(0xffffffffu, s, off);
        if (lane == 0) g_t[j] = s;
    }
    __syncthreads();
}

__global__ void __launch_bounds__(NTHR, 1)
k_main(const float* __restrict__ puz, const void* __restrict__ Araw,
       const float* __restrict__ logz, float* __restrict__ out) {
    extern __shared__ double sh[];
    __shared__ double s_red[32];
    __shared__ double s_val;
    __shared__ int s_cnt;
    const int tid = threadIdx.x, bid = blockIdx.x;
    const int warp = tid >> 5, lane = tid & 31;
    unsigned tgt = 0;

    // ---- phase: dtype detect (block 0 reads first 16KB only: safe either way)
    if (bid == 0) {
        if (tid == 0) s_cnt = 0;
        __syncthreads();
        int c = 0;
        const unsigned* W = (const unsigned*)Araw;
        for (int i = tid; i < 4096; i += NTHR) {
            float v = __uint_as_float(W[i]);
            if (v >= 1.0f && v < 4.0f) c++;
        }
        atomicAdd(&s_cnt, c);
        __syncthreads();
        if (tid == 0) g_is64 = (s_cnt > 64) ? 1 : 0;
    }
    gsync(tgt);

    // ---- phase: widen A (+ exact hi/lo split) + init state
    {
        int is64 = g_is64;
        const double* Ad = (const double*)Araw;
        const float*  Af = (const float*)Araw;
        for (size_t i = (size_t)bid * NTHR + tid; i < (size_t)NEQ * NX; i += (size_t)NBLK * NTHR) {
            double v = is64 ? Ad[i] : (double)Af[i];
            g_A[i] = v;
            float h = (float)v;
            g_Ah[i] = h;
            g_Al[i] = (float)(v - (double)h);
        }
        int i = bid * NTHR + tid;
        if (i < NX) {
            g_q[i] = -(double)puz[i];
            g_z[i] = 1.0; g_lam[i] = 1.0;
            g_w[i] = exp((double)logz[i]);
        }
        if (i < NEQ) g_nu[i] = 0.0;
    }
    gsync(tgt);

    // ---- phase: transpose A -> g_AT (32x32 tiles)
    {
        int tx = tid & 31, ty = tid >> 5;
        for (int t = bid; t < (NX / 32) * (NEQ / 32); t += NBLK) {
            int j0 = (t % (NX / 32)) * 32, e0 = (t / (NX / 32)) * 32;
#pragma unroll
            for (int m = 0; m < 4; m++) {
                int e = e0 + ty + 8 * m;
                sh[(ty + 8 * m) * 33 + tx] = g_A[(size_t)e * NX + j0 + tx];
            }
            __syncthreads();
#pragma unroll
            for (int m = 0; m < 4; m++) {
                int j = j0 + ty + 8 * m;
                g_AT[(size_t)j * NEQ + e0 + tx] = sh[tx * 33 + ty + 8 * m];
            }
            __syncthreads();
        }
    }
    gsync(tgt);

    // ---- phase: b = A @ exp(log_z0)
    amv_phase(sh, 0, bid, tid, warp, lane);
    gsync(tgt);

    // =================== IPM loop ===================
    for (int it = 0; it < ITERS; it++) {
        // t = A^T nu
        atmv_phase(sh, 0, bid, tid, warp, lane);
        gsync(tgt);

        // pre A: partial dot(z,lam)
        if (bid < 16) {
            int i = bid * NTHR + tid;
            blk_sum_to(g_z[i] * g_lam[i], s_red, tid, &s_val);
            if (tid == 0) g_part[bid] = s_val;
        }
        gsync(tgt);

        // pre B: gap + residual vectors
        if (bid < 16) {
            double gap = 0;
#pragma unroll
            for (int j = 0; j < 16; j++) gap += g_part[j];
            gap /= (double)NX;
            int i = bid * NTHR + tid;
            double z = g_z[i], la = g_lam[i];
            double rd = MU * z + g_q[i] - la + g_t[i];
            double rc = z * la - SIG * gap;
            double Di = 1.0 / (MU + la / z);
            double rt = -rd - rc / z;
            g_rc[i] = rc; g_Dinv[i] = Di; g_rtil[i] = rt;
            g_w[i] = rt * Di + z;
        }
        gsync(tgt);

        // rhs = A@w - b ; plus split B = A*diag(Dinv) into fp32 hi/lo
        amv_phase(sh, 1, bid, tid, warp, lane);
        for (size_t i = (size_t)bid * NTHR + tid; i < (size_t)NEQ * NX; i += (size_t)NBLK * NTHR) {
            int k = (int)(i & (NX - 1));
            double v = g_A[i] * g_Dinv[k];
            float h = (float)v;
            g_Bh[i] = h;
            g_Bl[i] = (float)(v - (double)h);
        }
        gsync(tgt);

        // ADA lower-tri = A diag(Dinv) A^T  (300 32x32 tiles, df64 on FP32 pipe)
        {
            float* Ahs = (float*)sh;          // [32][33]
            float* Als = Ahs + 1056;
            float* Bhs = Als + 1056;
            float* Bls = Bhs + 1056;
            int tx = tid & 31, ty = tid >> 5;
            for (int t = bid; t < 300; t += NBLK) {
                int bi, bj; tri_map(t, bi, bj);
                int row0 = bi * 32, col0 = bj * 32;
                float h0 = 0, h1 = 0, h2 = 0, h3 = 0;
                float l0 = 0, l1 = 0, l2 = 0, l3 = 0;
                for (int k0 = 0; k0 < NX; k0 += 32) {
#pragma unroll
                    for (int m = 0; m < 4; m++) {
                        int i = ty + 8 * m;
                        size_t ra = (size_t)(row0 + i) * NX + k0 + tx;
                        size_t rb = (size_t)(col0 + i) * NX + k0 + tx;
                        Ahs[tx * 33 + i] = g_Ah[ra];
                        Als[tx * 33 + i] = g_Al[ra];
                        Bhs[tx * 33 + i] = g_Bh[rb];
                        Bls[tx * 33 + i] = g_Bl[rb];
                    }
                    __syncthreads();
#pragma unroll
                    for (int k = 0; k < 32; k++) {
                        float bh = Bhs[k * 33 + tx], bl = Bls[k * 33 + tx];
                        df_mac_fast(Ahs[k * 33 + ty],      Als[k * 33 + ty],      bh, bl, h0, l0);
                        df_mac_fast(Ahs[k * 33 + ty + 8],  Als[k * 33 + ty + 8],  bh, bl, h1, l1);
                        df_mac_fast(Ahs[k * 33 + ty + 16], Als[k * 33 + ty + 16], bh, bl, h2, l2);
                        df_mac_fast(Ahs[k * 33 + ty + 24], Als[k * 33 + ty + 24], bh, bl, h3, l3);
                    }
                    __syncthreads();
                }
                size_t base = (size_t)row0 * NEQ + col0 + tx;
                g_ADA[base + (size_t)(ty)      * NEQ] = (double)h0 + (double)l0;
                g_ADA[base + (size_t)(ty + 8)  * NEQ] = (double)h1 + (double)l1;
                g_ADA[base + (size_t)(ty + 16) * NEQ] = (double)h2 + (double)l2;
                g_ADA[base + (size_t)(ty + 24) * NEQ] = (double)h3 + (double)l3;
            }
        }
        gsync(tgt);

        // ---- Cholesky: 12 panels of 64 ----
        for (int p = 0; p < 12; p++) {
            int o = p * 64, rem = NEQ - o - 64;
            // potrf (block 0)
            if (bid == 0) {
                double* S = sh;  // [64][65]
                int c = tid & 63, r0 = tid >> 6;
#pragma unroll
                for (int m = 0; m < 16; m++) { int r = r0 + 4 * m; S[r * 65 + c] = g_ADA[(size_t)(o + r) * NEQ + o + c]; }
                __syncthreads();
                int l = tid >> 2, cc = tid & 3;
                for (int j = 0; j < 64; j++) {
                    if (tid == 0) S[j * 65 + j] = sqrt(fmax(S[j * 65 + j], 1e-300));
                    __syncthreads();
                    if (tid > j && tid < 64) S[tid * 65 + j] /= S[j * 65 + j];
                    __syncthreads();
                    if (l > j) {
                        double ljj = S[l * 65 + j];
                        for (int k = j + 1 + cc; k <= l; k += 4) S[l * 65 + k] -= ljj * S[k * 65 + j];
                    }
                    __syncthreads();
                }
#pragma unroll
                for (int m = 0; m < 16; m++) { int r = r0 + 4 * m; g_ADA[(size_t)(o + r) * NEQ + o + c] = S[r * 65 + c]; }
            }
            gsync(tgt);

            // trsm: L21 = A21 * L11^{-T}, 64-row chunks per block (smem-based)
            if (rem > 0 && bid < rem / 64) {
                double* L = sh;          // [64][65]
                double* X = sh + 4160;   // [64][65]
                int base = o + 64 + bid * 64;
                for (int i = tid; i < 4096; i += NTHR) {
                    int r = i >> 6, c = i & 63;
                    L[r * 65 + c] = g_ADA[(size_t)(o + r) * NEQ + o + c];
                    X[r * 65 + c] = g_ADA[(size_t)(base + r) * NEQ + o + c];
                }
                __syncthreads();
                if (tid < 64) {
                    int r = tid;
                    for (int j = 0; j < 64; j++) {
                        double s = X[r * 65 + j];
                        for (int k = 0; k < j; k++) s -= X[r * 65 + k] * L[j * 65 + k];
                        X[r * 65 + j] = s / L[j * 65 + j];
                    }
                }
                __syncthreads();
                for (int i = tid; i < 4096; i += NTHR) {
                    int r = i >> 6, c = i & 63;
                    g_ADA[(size_t)(base + r) * NEQ + o + c] = X[r * 65 + c];
                }
            }
            gsync(tgt);

            // syrk: trailing C -= L21 L21^T over lower 32x32 tiles, K=64 (df64)
            if (rem > 0) {
                int nb = rem / 32, nt = nb * (nb + 1) / 2;
                float* Ahs = (float*)sh;          // [64][33]
                float* Als = Ahs + 2112;
                float* Bhs = Als + 2112;
                float* Bls = Bhs + 2112;
                int tx = tid & 31, ty = tid >> 5;
                int kk = tid & 63, ii = tid >> 6;
                int o2 = o + 64;
                for (int t = bid; t < nt; t += NBLK) {
                    int bi, bj; tri_map(t, bi, bj);
                    int r0 = o2 + bi * 32, c0 = o2 + bj * 32;
#pragma unroll
                    for (int m = 0; m < 8; m++) {
                        int i = ii + 4 * m;
                        double va = g_ADA[(size_t)(r0 + i) * NEQ + o + kk];
                        double vb = g_ADA[(size_t)(c0 + i) * NEQ + o + kk];
                        float ha = (float)va, hb = (float)vb;
                        Ahs[kk * 33 + i] = ha;
                        Als[kk * 33 + i] = (float)(va - (double)ha);
                        Bhs[kk * 33 + i] = hb;
                        Bls[kk * 33 + i] = (float)(vb - (double)hb);
                    }
                    __syncthreads();
                    float h0 = 0, h1 = 0, h2 = 0, h3 = 0;
                    float l0 = 0, l1 = 0, l2 = 0, l3 = 0;
#pragma unroll
                    for (int k = 0; k < 64; k++) {
                        float bh = Bhs[k * 33 + tx], bl = Bls[k * 33 + tx];
                        df_mac_knuth(Ahs[k * 33 + ty],      Als[k * 33 + ty],      bh, bl, h0, l0);
                        df_mac_knuth(Ahs[k * 33 + ty + 8],  Als[k * 33 + ty + 8],  bh, bl, h1, l1);
                        df_mac_knuth(Ahs[k * 33 + ty + 16], Als[k * 33 + ty + 16], bh, bl, h2, l2);
                        df_mac_knuth(Ahs[k * 33 + ty + 24], Als[k * 33 + ty + 24], bh, bl, h3, l3);
                    }
                    size_t basew = (size_t)r0 * NEQ + c0 + tx;
                    g_ADA[basew + (size_t)(ty)      * NEQ] -= ((double)h0 + (double)l0);
                    g_ADA[basew + (size_t)(ty + 8)  * NEQ] -= ((double)h1 + (double)l1);
                    g_ADA[basew + (size_t)(ty + 16) * NEQ] -= ((double)h2 + (double)l2);
                    g_ADA[basew + (size_t)(ty + 24) * NEQ] -= ((double)h3 + (double)l3);
                    __syncthreads();
                }
            }
            gsync(tgt);
        }

        // ---- triangular solves (block 0, 256 threads) ----
        if (bid == 0) {
            double* S = sh;          // [64][65]
            double* y = sh + 4160;   // [768]
            for (int i = tid; i < NEQ; i += NTHR) y[i] = g_rhs[i];
            __syncthreads();
            // forward
            for (int p = 0; p < 12; p++) {
                int o = p * 64;
                for (int i = tid; i < 4096; i += NTHR) {
                    int r = i >> 6, c = i & 63;
                    S[r * 65 + c] = g_ADA[(size_t)(o + r) * NEQ + o + c];
                }
                __syncthreads();
                for (int j = 0; j < 64; j++) {
                    if (tid == 0) y[o + j] /= S[j * 65 + j];
                    __syncthreads();
                    double yj = y[o + j];
                    if (tid > j && tid < 64) y[o + tid] -= S[tid * 65 + j] * yj;
                    __syncthreads();
                }
                for (int r = o + 64 + warp; r < NEQ; r += 8) {
                    double s = 0.0;
#pragma unroll
                    for (int k = lane; k < 64; k += 32) s += g_ADA[(size_t)r * NEQ + o + k] * y[o + k];
#pragma unroll
                    for (int off = 16; off; off >>= 1) s += __shfl_down_sync(0xffffffffu, s, off);
                    if (lane == 0) y[r] -= s;
                }
                __syncthreads();
            }
            // backward
            for (int p = 11; p >= 0; p--) {
                int o = p * 64;
                for (int i = tid; i < 4096; i += NTHR) {
                    int r = i >> 6, c = i & 63;
                    S[r * 65 + c] = g_ADA[(size_t)(o + r) * NEQ + o + c];
                }
                __syncthreads();
                for (int j = 63; j >= 0; j--) {
                    if (tid == 0) y[o + j] /= S[j * 65 + j];
                    __syncthreads();
                    double xj = y[o + j];
                    if (tid < j) y[o + tid] -= S[j * 65 + tid] * xj;
                    __syncthreads();
                }
                for (int i = tid; i < o; i += NTHR) {
                    double s = 0.0;
#pragma unroll 8
                    for (int jj = 0; jj < 64; jj++) s += g_ADA[(size_t)(o + jj) * NEQ + i] * y[o + jj];
                    y[i] -= s;
                }
                __syncthreads();
            }
            for (int i = tid; i < NEQ; i += NTHR) g_dnu[i] = y[i];
        }
        gsync(tgt);

        // t = A^T dnu
        atmv_phase(sh, 1, bid, tid, warp, lane);
        gsync(tgt);

        // step A: dz, dlam, partial min
        if (bid < 16) {
            int i = bid * NTHR + tid;
            double rt = g_rtil[i], t2 = g_t[i], Di = g_Dinv[i];
            double rc = g_rc[i], la = g_lam[i], zz = g_z[i];
            double dz = (rt - t2) * Di;
            double dl = (-rc - la * dz) / zz;
            g_dz[i] = dz; g_dlam[i] = dl;
            double mn = INFINITY;
            if (dz < 0.0) mn = fmin(mn, -zz / dz);
            if (dl < 0.0) mn = fmin(mn, -la / dl);
            blk_min_to(mn, s_red, tid, &s_val);
            if (tid == 0) g_pmin[bid] = s_val;
        }
        gsync(tgt);

        // step B: alpha + update z, lam, nu
        {
            double a = INFINITY;
#pragma unroll
            for (int j = 0; j < 16; j++) a = fmin(a, g_pmin[j]);
            a = fmin(1.0, 0.99 * a);
            if (bid < 16) {
                int i = bid * NTHR + tid;
                g_z[i]   += a * g_dz[i];
                g_lam[i] += a * g_dlam[i];
            } else if (bid < 19) {
                int i = (bid - 16) * NTHR + tid;
                if (i < NEQ) g_nu[i] += a * g_dnu[i];
            }
        }
        gsync(tgt);
    }

    // ---- output ----
    if (bid < 16) {
        int i = bid * NTHR + tid;
        out[i] = (float)g_z[i];
    }
}

// ---------------- host launcher (2 graph nodes) ----------------
extern "C" void kernel_launch(void* const* d_in, const int* in_sizes, int n_in,
                              void* d_out, int out_size) {
    const float* puz  = (const float*)d_in[0];
    const void*  Araw = d_in[1];
    const float* logz = (const float*)d_in[2];
    float* out = (float*)d_out;

    static int attr_set = 0;
    if (!attr_set) {
        cudaFuncSetAttribute(k_main, cudaFuncAttributeMaxDynamicSharedMemorySize,
                             SMEM_DBL * (int)sizeof(double));
        attr_set = 1;
    }

    k_reset<<<1, 1>>>();
    k_main<<<NBLK, NTHR, SMEM_DBL * sizeof(double)>>>(puz, Araw, logz, out);
}

// round 9
// speedup vs baseline: 2.8968x; 1.1727x over previous
#include <cuda_runtime.h>
#include <math.h>

#define NX    4096
#define NEQ   768
#define MU    0.1
#define SIG   0.1
#define ITERS 40
#define NBLK  132
#define NTHR  256
#define SMEM_DBL 8320          // 66560 bytes dynamic shared

// ---------------- device-global state ----------------
__device__ double g_A[(size_t)NEQ * NX];
__device__ double g_AT[(size_t)NX * NEQ];
__device__ float  g_Ah[(size_t)NEQ * NX];   // A split hi
__device__ float  g_Al[(size_t)NEQ * NX];   // A split lo
__device__ float  g_Bh[(size_t)NEQ * NX];   // (A * Dinv) split hi, per iteration
__device__ float  g_Bl[(size_t)NEQ * NX];   // (A * Dinv) split lo
__device__ double g_q[NX];
__device__ double g_b[NEQ];
__device__ double g_z[NX];
__device__ double g_lam[NX];
__device__ double g_nu[NEQ];
__device__ double g_t[NX];
__device__ double g_rc[NX];
__device__ double g_Dinv[NX];
__device__ double g_rtil[NX];
__device__ double g_w[NX];
__device__ double g_dnu[NEQ];
__device__ double g_rhs[NEQ];
__device__ double g_ADA[NEQ * NEQ];
__device__ double g_dz[NX];
__device__ double g_dlam[NX];
__device__ double g_part[16];
__device__ double g_pmin[16];
__device__ int    g_is64;
__device__ unsigned g_count;

__global__ void k_reset() { g_count = 0u; }

// software grid barrier
__device__ __forceinline__ void gsync(unsigned &tgt) {
    __syncthreads();
    __threadfence();
    if (threadIdx.x == 0) {
        atomicAdd(&g_count, 1u);
        tgt += NBLK;
        while (atomicAdd(&g_count, 0u) < tgt) __nanosleep(64);
    }
    __syncthreads();
    __threadfence();
}

__device__ __forceinline__ void blk_sum_to(double v, double* s_red, int tid, double* dst) {
#pragma unroll
    for (int off = 16; off; off >>= 1) v += __shfl_down_sync(0xffffffffu, v, off);
    if ((tid & 31) == 0) s_red[tid >> 5] = v;
    __syncthreads();
    if (tid == 0) { double r = 0; for (int w = 0; w < 8; w++) r += s_red[w]; *dst = r; }
    __syncthreads();
}
__device__ __forceinline__ void blk_min_to(double v, double* s_red, int tid, double* dst) {
#pragma unroll
    for (int off = 16; off; off >>= 1) v = fmin(v, __shfl_down_sync(0xffffffffu, v, off));
    if ((tid & 31) == 0) s_red[tid >> 5] = v;
    __syncthreads();
    if (tid == 0) { double r = s_red[0]; for (int w = 1; w < 8; w++) r = fmin(r, s_red[w]); *dst = r; }
    __syncthreads();
}

__device__ __forceinline__ void tri_map(int t, int &bi, int &bj) {
    int b = 0;
    while ((b + 1) * (b + 2) / 2 <= t) b++;
    bi = b; bj = t - b * (b + 1) / 2;
}

// A @ w  (mode 0 -> g_b ; mode 1 -> g_rhs = A@w - b)
__device__ __forceinline__ void amv_phase(double* sv, int mode, int bid, int tid, int warp, int lane) {
    for (int i = tid; i < NX; i += NTHR) sv[i] = g_w[i];
    __syncthreads();
    int row = bid * 8 + warp;
    if (row < NEQ) {
        const double* ar = g_A + (size_t)row * NX;
        double s = 0.0;
        for (int k = lane; k < NX; k += 32) s += ar[k] * sv[k];
#pragma unroll
        for (int off = 16; off; off >>= 1) s += __shfl_down_sync(0xffffffffu, s, off);
        if (lane == 0) { if (mode == 0) g_b[row] = s; else g_rhs[row] = s - g_b[row]; }
    }
    __syncthreads();
}

// g_t = A^T @ (mode ? dnu : nu)
__device__ __forceinline__ void atmv_phase(double* sx, int mode, int bid, int tid, int warp, int lane) {
    const double* x = mode ? g_dnu : g_nu;
    for (int i = tid; i < NEQ; i += NTHR) sx[i] = x[i];
    __syncthreads();
    for (int j = bid * 8 + warp; j < NX; j += NBLK * 8) {
        const double* ar = g_AT + (size_t)j * NEQ;
        double s = 0.0;
        for (int e = lane; e < NEQ; e += 32) s += ar[e] * sx[e];
#pragma unroll
        for (int off = 16; off; off >>= 1) s += __shfl_down_sync(0xffffffffu, s, off);
        if (lane == 0) g_t[j] = s;
    }
    __syncthreads();
}

__global__ void __launch_bounds__(NTHR, 1)
k_main(const float* __restrict__ puz, const void* __restrict__ Araw,
       const float* __restrict__ logz, float* __restrict__ out) {
    extern __shared__ double sh[];
    __shared__ double s_red[32];
    __shared__ double s_val;
    __shared__ int s_cnt;
    const int tid = threadIdx.x, bid = blockIdx.x;
    const int warp = tid >> 5, lane = tid & 31;
    unsigned tgt = 0;

    // ---- dtype detect (block 0 reads first 16KB only)
    if (bid == 0) {
        if (tid == 0) s_cnt = 0;
        __syncthreads();
        int c = 0;
        const unsigned* W = (const unsigned*)Araw;
        for (int i = tid; i < 4096; i += NTHR) {
            float v = __uint_as_float(W[i]);
            if (v >= 1.0f && v < 4.0f) c++;
        }
        atomicAdd(&s_cnt, c);
        __syncthreads();
        if (tid == 0) g_is64 = (s_cnt > 64) ? 1 : 0;
    }
    gsync(tgt);

    // ---- widen A + split + init state
    {
        int is64 = g_is64;
        const double* Ad = (const double*)Araw;
        const float*  Af = (const float*)Araw;
        for (size_t i = (size_t)bid * NTHR + tid; i < (size_t)NEQ * NX; i += (size_t)NBLK * NTHR) {
            double v = is64 ? Ad[i] : (double)Af[i];
            g_A[i] = v;
            float h = (float)v;
            g_Ah[i] = h;
            g_Al[i] = (float)(v - (double)h);
        }
        int i = bid * NTHR + tid;
        if (i < NX) {
            g_q[i] = -(double)puz[i];
            g_z[i] = 1.0; g_lam[i] = 1.0;
            g_w[i] = exp((double)logz[i]);
        }
        if (i < NEQ) g_nu[i] = 0.0;
    }
    gsync(tgt);

    // ---- transpose A -> g_AT
    {
        int tx = tid & 31, ty = tid >> 5;
        for (int t = bid; t < (NX / 32) * (NEQ / 32); t += NBLK) {
            int j0 = (t % (NX / 32)) * 32, e0 = (t / (NX / 32)) * 32;
#pragma unroll
            for (int m = 0; m < 4; m++) {
                int e = e0 + ty + 8 * m;
                sh[(ty + 8 * m) * 33 + tx] = g_A[(size_t)e * NX + j0 + tx];
            }
            __syncthreads();
#pragma unroll
            for (int m = 0; m < 4; m++) {
                int j = j0 + ty + 8 * m;
                g_AT[(size_t)j * NEQ + e0 + tx] = sh[tx * 33 + ty + 8 * m];
            }
            __syncthreads();
        }
    }
    gsync(tgt);

    // ---- b = A @ exp(log_z0)
    amv_phase(sh, 0, bid, tid, warp, lane);
    gsync(tgt);

    // =================== IPM loop ===================
    for (int it = 0; it < ITERS; it++) {
        atmv_phase(sh, 0, bid, tid, warp, lane);
        gsync(tgt);

        if (bid < 16) {
            int i = bid * NTHR + tid;
            blk_sum_to(g_z[i] * g_lam[i], s_red, tid, &s_val);
            if (tid == 0) g_part[bid] = s_val;
        }
        gsync(tgt);

        if (bid < 16) {
            double gap = 0;
#pragma unroll
            for (int j = 0; j < 16; j++) gap += g_part[j];
            gap /= (double)NX;
            int i = bid * NTHR + tid;
            double z = g_z[i], la = g_lam[i];
            double rd = MU * z + g_q[i] - la + g_t[i];
            double rc = z * la - SIG * gap;
            double Di = 1.0 / (MU + la / z);
            double rt = -rd - rc / z;
            g_rc[i] = rc; g_Dinv[i] = Di; g_rtil[i] = rt;
            g_w[i] = rt * Di + z;
        }
        gsync(tgt);

        // rhs = A@w - b ; split B = A*diag(Dinv)
        amv_phase(sh, 1, bid, tid, warp, lane);
        for (size_t i = (size_t)bid * NTHR + tid; i < (size_t)NEQ * NX; i += (size_t)NBLK * NTHR) {
            int k = (int)(i & (NX - 1));
            double v = g_A[i] * g_Dinv[k];
            float h = (float)v;
            g_Bh[i] = h;
            g_Bl[i] = (float)(v - (double)h);
        }
        gsync(tgt);

        // ---- Gram: ADA = A D A^T, 64x64 tiles (78 = 1 wave), df64 on FP32 pipe
        {
            const int is64 = g_is64;
            float* Ahs = (float*)sh;         // [32][68]
            float* Als = Ahs + 2176;
            float* Bhs = Als + 2176;
            float* Bls = Bhs + 2176;
            const int txc = (tid & 15) * 4;
            const int tyr = (tid >> 4) * 4;
            for (int t = bid; t < 78; t += NBLK) {
                int bi, bj; tri_map(t, bi, bj);
                int row0 = bi * 64, col0 = bj * 64;
                float Hh[4][4] = {{0}}, Hl[4][4] = {{0}};
                for (int k0 = 0; k0 < NX; k0 += 32) {
                    for (int r = warp; r < 64; r += 8) {
                        size_t ga = (size_t)(row0 + r) * NX + k0 + lane;
                        size_t gb = (size_t)(col0 + r) * NX + k0 + lane;
                        Ahs[lane * 68 + r] = g_Ah[ga];
                        if (is64) Als[lane * 68 + r] = g_Al[ga];
                        Bhs[lane * 68 + r] = g_Bh[gb];
                        Bls[lane * 68 + r] = g_Bl[gb];
                    }
                    __syncthreads();
                    if (!is64) {
#pragma unroll 4
                        for (int k = 0; k < 32; k++) {
                            float4 a4 = *(const float4*)(Ahs + k * 68 + tyr);
                            float4 bh4 = *(const float4*)(Bhs + k * 68 + txc);
                            float4 bl4 = *(const float4*)(Bls + k * 68 + txc);
                            float av[4] = {a4.x, a4.y, a4.z, a4.w};
                            float bh[4] = {bh4.x, bh4.y, bh4.z, bh4.w};
                            float bl[4] = {bl4.x, bl4.y, bl4.z, bl4.w};
#pragma unroll
                            for (int r = 0; r < 4; r++)
#pragma unroll
                                for (int c = 0; c < 4; c++) {
                                    float p = __fmul_rn(av[r], bh[c]);
                                    float e = __fmaf_rn(av[r], bh[c], -p);
                                    e = __fmaf_rn(av[r], bl[c], e);
                                    float ts = __fadd_rn(Hh[r][c], p);
                                    float e2 = __fadd_rn(__fsub_rn(Hh[r][c], ts), p);
                                    Hh[r][c] = ts;
                                    Hl[r][c] = __fadd_rn(Hl[r][c], __fadd_rn(e, e2));
                                }
                        }
                    } else {
#pragma unroll 4
                        for (int k = 0; k < 32; k++) {
                            float4 a4 = *(const float4*)(Ahs + k * 68 + tyr);
                            float4 al4 = *(const float4*)(Als + k * 68 + tyr);
                            float4 bh4 = *(const float4*)(Bhs + k * 68 + txc);
                            float4 bl4 = *(const float4*)(Bls + k * 68 + txc);
                            float av[4] = {a4.x, a4.y, a4.z, a4.w};
                            float alv[4] = {al4.x, al4.y, al4.z, al4.w};
                            float bh[4] = {bh4.x, bh4.y, bh4.z, bh4.w};
                            float bl[4] = {bl4.x, bl4.y, bl4.z, bl4.w};
#pragma unroll
                            for (int r = 0; r < 4; r++)
#pragma unroll
                                for (int c = 0; c < 4; c++) {
                                    float p = __fmul_rn(av[r], bh[c]);
                                    float e = __fmaf_rn(av[r], bh[c], -p);
                                    e = __fmaf_rn(av[r], bl[c], e);
                                    e = __fmaf_rn(alv[r], bh[c], e);
                                    float ts = __fadd_rn(Hh[r][c], p);
                                    float e2 = __fadd_rn(__fsub_rn(Hh[r][c], ts), p);
                                    Hh[r][c] = ts;
                                    Hl[r][c] = __fadd_rn(Hl[r][c], __fadd_rn(e, e2));
                                }
                        }
                    }
                    __syncthreads();
                }
#pragma unroll
                for (int r = 0; r < 4; r++)
#pragma unroll
                    for (int c = 0; c < 4; c++)
                        g_ADA[(size_t)(row0 + tyr + r) * NEQ + col0 + txc + c] =
                            (double)Hh[r][c] + (double)Hl[r][c];
            }
        }
        gsync(tgt);

        // ---- Cholesky: 12 panels of 64 ----
        for (int p = 0; p < 12; p++) {
            int o = p * 64, rem = NEQ - o - 64;

            // potrf (block 0): j-sweep, rank-1 trailing update with all threads
            if (bid == 0) {
                double* S = sh;                 // [64][65]; bcast at S[4160]
                for (int i = tid; i < 4096; i += NTHR) {
                    int r = i >> 6, c = i & 63;
                    S[r * 65 + c] = g_ADA[(size_t)(o + r) * NEQ + o + c];
                }
                __syncthreads();
                int r = tid & 63, q = tid >> 6;
                for (int j = 0; j < 64; j++) {
                    if (tid == 0) {
                        double s = sqrt(fmax(S[j * 65 + j], 1e-300));
                        S[j * 65 + j] = s;
                        S[4160] = 1.0 / s;
                    }
                    __syncthreads();
                    if (q == 0 && r > j) S[r * 65 + j] *= S[4160];
                    __syncthreads();
                    if (r > j) {
                        double lr = S[r * 65 + j];
                        for (int c = j + 1 + q; c <= r; c += 4)
                            S[r * 65 + c] -= lr * S[c * 65 + j];
                    }
                    __syncthreads();
                }
                for (int i = tid; i < 4096; i += NTHR) {
                    int rr = i >> 6, c = i & 63;
                    g_ADA[(size_t)(o + rr) * NEQ + o + c] = S[rr * 65 + c];
                }
            }
            gsync(tgt);

            // trsm: column-sweep, 64-row chunks per block
            if (rem > 0 && bid < rem / 64) {
                double* L = sh;          // [64][65]
                double* X = sh + 4160;   // [64][65]
                int base = o + 64 + bid * 64;
                for (int i = tid; i < 4096; i += NTHR) {
                    int r = i >> 6, c = i & 63;
                    L[r * 65 + c] = g_ADA[(size_t)(o + r) * NEQ + o + c];
                    X[r * 65 + c] = g_ADA[(size_t)(base + r) * NEQ + o + c];
                }
                __syncthreads();
                if (tid < 64) L[tid * 65 + tid] = 1.0 / L[tid * 65 + tid];
                __syncthreads();
                int r = tid & 63, q = tid >> 6;
                for (int j = 0; j < 64; j++) {
                    if (q == 0) X[r * 65 + j] *= L[j * 65 + j];
                    __syncthreads();
                    double xj = X[r * 65 + j];
                    for (int c = j + 1 + q; c < 64; c += 4)
                        X[r * 65 + c] -= xj * L[c * 65 + j];
                    __syncthreads();
                }
                for (int i = tid; i < 4096; i += NTHR) {
                    int rr = i >> 6, c = i & 63;
                    g_ADA[(size_t)(base + rr) * NEQ + o + c] = X[rr * 65 + c];
                }
            }
            gsync(tgt);

            // syrk: trailing C -= L21 L21^T, 64x64 tiles, df64 (knuth)
            if (rem > 0) {
                int nb = rem / 64, nt = nb * (nb + 1) / 2;
                float* Ahs = (float*)sh;       // [32][68]
                float* Als = Ahs + 2176;
                float* Bhs = Als + 2176;
                float* Bls = Bhs + 2176;
                const int txc = (tid & 15) * 4;
                const int tyr = (tid >> 4) * 4;
                int o2 = o + 64;
                for (int t = bid; t < nt; t += NBLK) {
                    int bi, bj; tri_map(t, bi, bj);
                    int r0 = o2 + bi * 64, c0 = o2 + bj * 64;
                    float Hh[4][4] = {{0}}, Hl[4][4] = {{0}};
                    for (int kq = 0; kq < 64; kq += 32) {
                        for (int r = warp; r < 64; r += 8) {
                            double va = g_ADA[(size_t)(r0 + r) * NEQ + o + kq + lane];
                            double vb = g_ADA[(size_t)(c0 + r) * NEQ + o + kq + lane];
                            float ha = (float)va, hb = (float)vb;
                            Ahs[lane * 68 + r] = ha;
                            Als[lane * 68 + r] = (float)(va - (double)ha);
                            Bhs[lane * 68 + r] = hb;
                            Bls[lane * 68 + r] = (float)(vb - (double)hb);
                        }
                        __syncthreads();
#pragma unroll 4
                        for (int k = 0; k < 32; k++) {
                            float4 a4 = *(const float4*)(Ahs + k * 68 + tyr);
                            float4 al4 = *(const float4*)(Als + k * 68 + tyr);
                            float4 bh4 = *(const float4*)(Bhs + k * 68 + txc);
                            float4 bl4 = *(const float4*)(Bls + k * 68 + txc);
                            float av[4] = {a4.x, a4.y, a4.z, a4.w};
                            float alv[4] = {al4.x, al4.y, al4.z, al4.w};
                            float bh[4] = {bh4.x, bh4.y, bh4.z, bh4.w};
                            float bl[4] = {bl4.x, bl4.y, bl4.z, bl4.w};
#pragma unroll
                            for (int r = 0; r < 4; r++)
#pragma unroll
                                for (int c = 0; c < 4; c++) {
                                    float p = __fmul_rn(av[r], bh[c]);
                                    float e = __fmaf_rn(av[r], bh[c], -p);
                                    e = __fmaf_rn(av[r], bl[c], e);
                                    e = __fmaf_rn(alv[r], bh[c], e);
                                    float s = __fadd_rn(Hh[r][c], p);
                                    float bb = __fsub_rn(s, Hh[r][c]);
                                    float err = __fadd_rn(__fsub_rn(Hh[r][c], __fsub_rn(s, bb)),
                                                          __fsub_rn(p, bb));
                                    Hh[r][c] = s;
                                    Hl[r][c] = __fadd_rn(Hl[r][c], __fadd_rn(e, err));
                                }
                        }
                        __syncthreads();
                    }
#pragma unroll
                    for (int r = 0; r < 4; r++)
#pragma unroll
                        for (int c = 0; c < 4; c++)
                            g_ADA[(size_t)(r0 + tyr + r) * NEQ + c0 + txc + c] -=
                                ((double)Hh[r][c] + (double)Hl[r][c]);
                }
            }
            gsync(tgt);
        }

        // ---- triangular solves (block 0) ----
        if (bid == 0) {
            double* S = sh;          // [64][65]
            double* y = sh + 4160;   // [768]
            for (int i = tid; i < NEQ; i += NTHR) y[i] = g_rhs[i];
            __syncthreads();
            for (int p = 0; p < 12; p++) {
                int o = p * 64;
                for (int i = tid; i < 4096; i += NTHR) {
                    int r = i >> 6, c = i & 63;
                    S[r * 65 + c] = g_ADA[(size_t)(o + r) * NEQ + o + c];
                }
                __syncthreads();
                for (int j = 0; j < 64; j++) {
                    if (tid == 0) y[o + j] /= S[j * 65 + j];
                    __syncthreads();
                    double yj = y[o + j];
                    if (tid > j && tid < 64) y[o + tid] -= S[tid * 65 + j] * yj;
                    __syncthreads();
                }
                for (int r = o + 64 + warp; r < NEQ; r += 8) {
                    double s = 0.0;
#pragma unroll
                    for (int k = lane; k < 64; k += 32) s += g_ADA[(size_t)r * NEQ + o + k] * y[o + k];
#pragma unroll
                    for (int off = 16; off; off >>= 1) s += __shfl_down_sync(0xffffffffu, s, off);
                    if (lane == 0) y[r] -= s;
                }
                __syncthreads();
            }
            for (int p = 11; p >= 0; p--) {
                int o = p * 64;
                for (int i = tid; i < 4096; i += NTHR) {
                    int r = i >> 6, c = i & 63;
                    S[r * 65 + c] = g_ADA[(size_t)(o + r) * NEQ + o + c];
                }
                __syncthreads();
                for (int j = 63; j >= 0; j--) {
                    if (tid == 0) y[o + j] /= S[j * 65 + j];
                    __syncthreads();
                    double xj = y[o + j];
                    if (tid < j) y[o + tid] -= S[j * 65 + tid] * xj;
                    __syncthreads();
                }
                for (int i = tid; i < o; i += NTHR) {
                    double s = 0.0;
#pragma unroll 8
                    for (int jj = 0; jj < 64; jj++) s += g_ADA[(size_t)(o + jj) * NEQ + i] * y[o + jj];
                    y[i] -= s;
                }
                __syncthreads();
            }
            for (int i = tid; i < NEQ; i += NTHR) g_dnu[i] = y[i];
        }
        gsync(tgt);

        atmv_phase(sh, 1, bid, tid, warp, lane);
        gsync(tgt);

        if (bid < 16) {
            int i = bid * NTHR + tid;
            double rt = g_rtil[i], t2 = g_t[i], Di = g_Dinv[i];
            double rc = g_rc[i], la = g_lam[i], zz = g_z[i];
            double dz = (rt - t2) * Di;
            double dl = (-rc - la * dz) / zz;
            g_dz[i] = dz; g_dlam[i] = dl;
            double mn = INFINITY;
            if (dz < 0.0) mn = fmin(mn, -zz / dz);
            if (dl < 0.0) mn = fmin(mn, -la / dl);
            blk_min_to(mn, s_red, tid, &s_val);
            if (tid == 0) g_pmin[bid] = s_val;
        }
        gsync(tgt);

        {
            double a = INFINITY;
#pragma unroll
            for (int j = 0; j < 16; j++) a = fmin(a, g_pmin[j]);
            a = fmin(1.0, 0.99 * a);
            if (bid < 16) {
                int i = bid * NTHR + tid;
                g_z[i]   += a * g_dz[i];
                g_lam[i] += a * g_dlam[i];
            } else if (bid < 19) {
                int i = (bid - 16) * NTHR + tid;
                if (i < NEQ) g_nu[i] += a * g_dnu[i];
            }
        }
        gsync(tgt);
    }

    if (bid < 16) {
        int i = bid * NTHR + tid;
        out[i] = (float)g_z[i];
    }
}

// ---------------- host launcher (2 graph nodes) ----------------
extern "C" void kernel_launch(void* const* d_in, const int* in_sizes, int n_in,
                              void* d_out, int out_size) {
    const float* puz  = (const float*)d_in[0];
    const void*  Araw = d_in[1];
    const float* logz = (const float*)d_in[2];
    float* out = (float*)d_out;

    static int attr_set = 0;
    if (!attr_set) {
        cudaFuncSetAttribute(k_main, cudaFuncAttributeMaxDynamicSharedMemorySize,
                             SMEM_DBL * (int)sizeof(double));
        attr_set = 1;
    }

    k_reset<<<1, 1>>>();
    k_main<<<NBLK, NTHR, SMEM_DBL * sizeof(double)>>>(puz, Araw, logz, out);
}

// round 12
// speedup vs baseline: 3.3267x; 1.1484x over previous
#include <cuda_runtime.h>
#include <math.h>

#define NX    4096
#define NEQ   768
#define MU    0.1
#define SIG   0.1
#define ITERS 40
#define NBLK  132
#define NTHR  256
#define SMEM_DBL 8320          // 66560 bytes dynamic shared

// ---------------- device-global state ----------------
__device__ double g_A[(size_t)NEQ * NX];
__device__ double g_AT[(size_t)NX * NEQ];
__device__ float  g_Ah[(size_t)NEQ * NX];
__device__ float  g_Al[(size_t)NEQ * NX];
__device__ float  g_Bh[(size_t)NEQ * NX];
__device__ float  g_Bl[(size_t)NEQ * NX];
__device__ double g_q[NX];
__device__ double g_b[NEQ];
__device__ double g_z[NX];
__device__ double g_lam[NX];
__device__ double g_nu[NEQ];
__device__ double g_t[NX];
__device__ double g_rc[NX];
__device__ double g_Dinv[NX];
__device__ double g_rtil[NX];
__device__ double g_w[NX];
__device__ double g_dnu[NEQ];
__device__ double g_rhs[NEQ];
__device__ double g_ADA[NEQ * NEQ];
__device__ double g_invd[NEQ];       // 1/L[j][j] per factored column
__device__ double g_dz[NX];
__device__ double g_dlam[NX];
__device__ double g_part[16];
__device__ double g_pmin[16];
__device__ int    g_is64;
__device__ unsigned g_count;

__global__ void k_reset() { g_count = 0u; }

// software grid barrier: arrive with atomic, poll with plain L2 load
__device__ __forceinline__ void gsync(unsigned &tgt) {
    __syncthreads();
    if (threadIdx.x == 0) {
        __threadfence();
        atomicAdd(&g_count, 1u);
        tgt += NBLK;
        while (*(volatile unsigned*)&g_count < tgt) __nanosleep(32);
        __threadfence();
    }
    __syncthreads();
}

__device__ __forceinline__ void blk_sum_to(double v, double* s_red, int tid, double* dst) {
#pragma unroll
    for (int off = 16; off; off >>= 1) v += __shfl_down_sync(0xffffffffu, v, off);
    if ((tid & 31) == 0) s_red[tid >> 5] = v;
    __syncthreads();
    if (tid == 0) { double r = 0; for (int w = 0; w < 8; w++) r += s_red[w]; *dst = r; }
    __syncthreads();
}
__device__ __forceinline__ void blk_min_to(double v, double* s_red, int tid, double* dst) {
#pragma unroll
    for (int off = 16; off; off >>= 1) v = fmin(v, __shfl_down_sync(0xffffffffu, v, off));
    if ((tid & 31) == 0) s_red[tid >> 5] = v;
    __syncthreads();
    if (tid == 0) { double r = s_red[0]; for (int w = 1; w < 8; w++) r = fmin(r, s_red[w]); *dst = r; }
    __syncthreads();
}

__device__ __forceinline__ void tri_map(int t, int &bi, int &bj) {
    int b = 0;
    while ((b + 1) * (b + 2) / 2 <= t) b++;
    bi = b; bj = t - b * (b + 1) / 2;
}

// range-safe fp64 reciprocal: integer magic seed (~9% max err, full exponent range)
// + 4 fused Newton steps -> ~1-2 ulp. No fp32 under/overflow hazard.
__device__ __forceinline__ double fast_rcp(double d) {
    double r = __longlong_as_double(0x7FDE6238502484BAll - __double_as_longlong(d));
#pragma unroll
    for (int s = 0; s < 4; s++) {
        double e = __fma_rn(-d, r, 1.0);
        r = __fma_rn(r, e, r);
    }
    return r;
}

// A @ w  (mode 0 -> g_b ; mode 1 -> g_rhs = A@w - b)
__device__ __forceinline__ void amv_phase(double* sv, int mode, int bid, int tid, int warp, int lane) {
    for (int i = tid; i < NX; i += NTHR) sv[i] = g_w[i];
    __syncthreads();
    int row = bid * 8 + warp;
    if (row < NEQ) {
        const double* ar = g_A + (size_t)row * NX;
        double s = 0.0;
        for (int k = lane; k < NX; k += 32) s += ar[k] * sv[k];
#pragma unroll
        for (int off = 16; off; off >>= 1) s += __shfl_down_sync(0xffffffffu, s, off);
        if (lane == 0) { if (mode == 0) g_b[row] = s; else g_rhs[row] = s - g_b[row]; }
    }
    __syncthreads();
}

// g_t = A^T @ (mode ? dnu : nu)
__device__ __forceinline__ void atmv_phase(double* sx, int mode, int bid, int tid, int warp, int lane) {
    const double* x = mode ? g_dnu : g_nu;
    for (int i = tid; i < NEQ; i += NTHR) sx[i] = x[i];
    __syncthreads();
    for (int j = bid * 8 + warp; j < NX; j += NBLK * 8) {
        const double* ar = g_AT + (size_t)j * NEQ;
        double s = 0.0;
        for (int e = lane; e < NEQ; e += 32) s += ar[e] * sx[e];
#pragma unroll
        for (int off = 16; off; off >>= 1) s += __shfl_down_sync(0xffffffffu, s, off);
        if (lane == 0) g_t[j] = s;
    }
    __syncthreads();
}

__global__ void __launch_bounds__(NTHR, 1)
k_main(const float* __restrict__ puz, const void* __restrict__ Araw,
       const float* __restrict__ logz, float* __restrict__ out) {
    extern __shared__ double sh[];
    __shared__ double s_red[32];
    __shared__ double s_val;
    __shared__ int s_cnt;
    const int tid = threadIdx.x, bid = blockIdx.x;
    const int warp = tid >> 5, lane = tid & 31;
    unsigned tgt = 0;

    // ---- dtype detect (block 0 reads first 16KB only)
    if (bid == 0) {
        if (tid == 0) s_cnt = 0;
        __syncthreads();
        int c = 0;
        const unsigned* W = (const unsigned*)Araw;
        for (int i = tid; i < 4096; i += NTHR) {
            float v = __uint_as_float(W[i]);
            if (v >= 1.0f && v < 4.0f) c++;
        }
        atomicAdd(&s_cnt, c);
        __syncthreads();
        if (tid == 0) g_is64 = (s_cnt > 64) ? 1 : 0;
    }
    gsync(tgt);

    // ---- widen A + split + init state
    {
        int is64 = g_is64;
        const double* Ad = (const double*)Araw;
        const float*  Af = (const float*)Araw;
        for (size_t i = (size_t)bid * NTHR + tid; i < (size_t)NEQ * NX; i += (size_t)NBLK * NTHR) {
            double v = is64 ? Ad[i] : (double)Af[i];
            g_A[i] = v;
            float h = (float)v;
            g_Ah[i] = h;
            g_Al[i] = (float)(v - (double)h);
        }
        int i = bid * NTHR + tid;
        if (i < NX) {
            g_q[i] = -(double)puz[i];
            g_z[i] = 1.0; g_lam[i] = 1.0;
            g_w[i] = exp((double)logz[i]);
        }
        if (i < NEQ) g_nu[i] = 0.0;
    }
    gsync(tgt);

    // ---- transpose A -> g_AT
    {
        int tx = tid & 31, ty = tid >> 5;
        for (int t = bid; t < (NX / 32) * (NEQ / 32); t += NBLK) {
            int j0 = (t % (NX / 32)) * 32, e0 = (t / (NX / 32)) * 32;
#pragma unroll
            for (int m = 0; m < 4; m++) {
                int e = e0 + ty + 8 * m;
                sh[(ty + 8 * m) * 33 + tx] = g_A[(size_t)e * NX + j0 + tx];
            }
            __syncthreads();
#pragma unroll
            for (int m = 0; m < 4; m++) {
                int j = j0 + ty + 8 * m;
                g_AT[(size_t)j * NEQ + e0 + tx] = sh[tx * 33 + ty + 8 * m];
            }
            __syncthreads();
        }
    }
    gsync(tgt);

    // ---- b = A @ exp(log_z0)
    amv_phase(sh, 0, bid, tid, warp, lane);
    gsync(tgt);

    // =================== IPM loop ===================
    for (int it = 0; it < ITERS; it++) {
        atmv_phase(sh, 0, bid, tid, warp, lane);
        gsync(tgt);

        if (bid < 16) {
            int i = bid * NTHR + tid;
            blk_sum_to(g_z[i] * g_lam[i], s_red, tid, &s_val);
            if (tid == 0) g_part[bid] = s_val;
        }
        gsync(tgt);

        if (bid < 16) {
            double gap = 0;
#pragma unroll
            for (int j = 0; j < 16; j++) gap += g_part[j];
            gap /= (double)NX;
            int i = bid * NTHR + tid;
            double z = g_z[i], la = g_lam[i];
            double rd = MU * z + g_q[i] - la + g_t[i];
            double rc = z * la - SIG * gap;
            double Di = 1.0 / (MU + la / z);
            double rt = -rd - rc / z;
            g_rc[i] = rc; g_Dinv[i] = Di; g_rtil[i] = rt;
            g_w[i] = rt * Di + z;
        }
        gsync(tgt);

        // rhs = A@w - b ; split B = A*diag(Dinv)
        amv_phase(sh, 1, bid, tid, warp, lane);
        for (size_t i = (size_t)bid * NTHR + tid; i < (size_t)NEQ * NX; i += (size_t)NBLK * NTHR) {
            int k = (int)(i & (NX - 1));
            double v = g_A[i] * g_Dinv[k];
            float h = (float)v;
            g_Bh[i] = h;
            g_Bl[i] = (float)(v - (double)h);
        }
        gsync(tgt);

        // ---- Gram: ADA = A D A^T, 64x64 tiles, df64 on FP32 pipe
        {
            const int is64 = g_is64;
            float* Ahs = (float*)sh;         // [32][68]
            float* Als = Ahs + 2176;
            float* Bhs = Als + 2176;
            float* Bls = Bhs + 2176;
            const int txc = (tid & 15) * 4;
            const int tyr = (tid >> 4) * 4;
            for (int t = bid; t < 78; t += NBLK) {
                int bi, bj; tri_map(t, bi, bj);
                int row0 = bi * 64, col0 = bj * 64;
                float Hh[4][4] = {{0}}, Hl[4][4] = {{0}};
                for (int k0 = 0; k0 < NX; k0 += 32) {
                    for (int r = warp; r < 64; r += 8) {
                        size_t ga = (size_t)(row0 + r) * NX + k0 + lane;
                        size_t gb = (size_t)(col0 + r) * NX + k0 + lane;
                        Ahs[lane * 68 + r] = g_Ah[ga];
                        if (is64) Als[lane * 68 + r] = g_Al[ga];
                        Bhs[lane * 68 + r] = g_Bh[gb];
                        Bls[lane * 68 + r] = g_Bl[gb];
                    }
                    __syncthreads();
                    if (!is64) {
#pragma unroll 4
                        for (int k = 0; k < 32; k++) {
                            float4 a4 = *(const float4*)(Ahs + k * 68 + tyr);
                            float4 bh4 = *(const float4*)(Bhs + k * 68 + txc);
                            float4 bl4 = *(const float4*)(Bls + k * 68 + txc);
                            float av[4] = {a4.x, a4.y, a4.z, a4.w};
                            float bh[4] = {bh4.x, bh4.y, bh4.z, bh4.w};
                            float bl[4] = {bl4.x, bl4.y, bl4.z, bl4.w};
#pragma unroll
                            for (int r = 0; r < 4; r++)
#pragma unroll
                                for (int c = 0; c < 4; c++) {
                                    float p = __fmul_rn(av[r], bh[c]);
                                    float e = __fmaf_rn(av[r], bh[c], -p);
                                    e = __fmaf_rn(av[r], bl[c], e);
                                    float ts = __fadd_rn(Hh[r][c], p);
                                    float e2 = __fadd_rn(__fsub_rn(Hh[r][c], ts), p);
                                    Hh[r][c] = ts;
                                    Hl[r][c] = __fadd_rn(Hl[r][c], __fadd_rn(e, e2));
                                }
                        }
                    } else {
#pragma unroll 4
                        for (int k = 0; k < 32; k++) {
                            float4 a4 = *(const float4*)(Ahs + k * 68 + tyr);
                            float4 al4 = *(const float4*)(Als + k * 68 + tyr);
                            float4 bh4 = *(const float4*)(Bhs + k * 68 + txc);
                            float4 bl4 = *(const float4*)(Bls + k * 68 + txc);
                            float av[4] = {a4.x, a4.y, a4.z, a4.w};
                            float alv[4] = {al4.x, al4.y, al4.z, al4.w};
                            float bh[4] = {bh4.x, bh4.y, bh4.z, bh4.w};
                            float bl[4] = {bl4.x, bl4.y, bl4.z, bl4.w};
#pragma unroll
                            for (int r = 0; r < 4; r++)
#pragma unroll
                                for (int c = 0; c < 4; c++) {
                                    float p = __fmul_rn(av[r], bh[c]);
                                    float e = __fmaf_rn(av[r], bh[c], -p);
                                    e = __fmaf_rn(av[r], bl[c], e);
                                    e = __fmaf_rn(alv[r], bh[c], e);
                                    float ts = __fadd_rn(Hh[r][c], p);
                                    float e2 = __fadd_rn(__fsub_rn(Hh[r][c], ts), p);
                                    Hh[r][c] = ts;
                                    Hl[r][c] = __fadd_rn(Hl[r][c], __fadd_rn(e, e2));
                                }
                        }
                    }
                    __syncthreads();
                }
#pragma unroll
                for (int r = 0; r < 4; r++)
#pragma unroll
                    for (int c = 0; c < 4; c++)
                        g_ADA[(size_t)(row0 + tyr + r) * NEQ + col0 + txc + c] =
                            (double)Hh[r][c] + (double)Hl[r][c];
            }
        }
        gsync(tgt);

        // ---- Cholesky: 12 panels of 64 ----
        for (int p = 0; p < 12; p++) {
            int o = p * 64, rem = NEQ - o - 64;

            // potrf (block 0): LDL^T-style rank-1 with range-safe Newton reciprocal;
            // deferred column scaling; stores g_invd = 1/L[j][j]
            if (bid == 0) {
                double* S   = sh;            // [64][65]
                double* wv  = sh + 4160;     // [64]
                double* inv = sh + 4224;     // [64]
                double* rsv = sh + 4288;     // [64]
                for (int i = tid; i < 4096; i += NTHR) {
                    int r = i >> 6, c = i & 63;
                    S[r * 65 + c] = g_ADA[(size_t)(o + r) * NEQ + o + c];
                }
                __syncthreads();
                int r = tid & 63, q = tid >> 6;
                for (int j = 0; j < 64; j++) {
                    if (q == 0) {
                        double d = fmax(S[j * 65 + j], 1e-300);
                        double ri = fast_rcp(d);         // redundant in all q0 threads
                        if (r == j) inv[j] = ri;
                        if (r > j) wv[r] = S[r * 65 + j] * ri;
                    }
                    __syncthreads();
                    if (r > j) {
                        double wr = wv[r];
                        for (int c = j + 1 + q; c <= r; c += 4)
                            S[r * 65 + c] -= wr * S[c * 65 + j];
                    }
                    __syncthreads();
                }
                // finalize: rs_j = sqrt(inv_j); L[r][j] = U[r][j]*rs_j; L[j][j] = d_j*rs_j
                if (tid < 64) {
                    double rs = sqrt(inv[tid]);
                    rsv[tid] = rs;
                    g_invd[o + tid] = rs;                 // = 1/L[j][j]
                }
                __syncthreads();
                for (int i = tid; i < 4096; i += NTHR) {
                    int rr = i >> 6, c = i & 63;
                    g_ADA[(size_t)(o + rr) * NEQ + o + c] = S[rr * 65 + c] * rsv[c];
                }
            }
            gsync(tgt);

            // trsm: column-sweep, reciprocal diag from g_invd
            if (rem > 0 && bid < rem / 64) {
                double* L = sh;          // [64][65]
                double* X = sh + 4160;   // [64][65]
                int base = o + 64 + bid * 64;
                for (int i = tid; i < 4096; i += NTHR) {
                    int r = i >> 6, c = i & 63;
                    L[r * 65 + c] = g_ADA[(size_t)(o + r) * NEQ + o + c];
                    X[r * 65 + c] = g_ADA[(size_t)(base + r) * NEQ + o + c];
                }
                __syncthreads();   // REQUIRED: load loop writes L[j][j] from a different thread
                if (tid < 64) L[tid * 65 + tid] = g_invd[o + tid];
                __syncthreads();
                int r = tid & 63, q = tid >> 6;
                for (int j = 0; j < 64; j++) {
                    if (q == 0) X[r * 65 + j] *= L[j * 65 + j];
                    __syncthreads();
                    double xj = X[r * 65 + j];
                    for (int c = j + 1 + q; c < 64; c += 4)
                        X[r * 65 + c] -= xj * L[c * 65 + j];
                    __syncthreads();
                }
                for (int i = tid; i < 4096; i += NTHR) {
                    int rr = i >> 6, c = i & 63;
                    g_ADA[(size_t)(base + rr) * NEQ + o + c] = X[rr * 65 + c];
                }
            }
            gsync(tgt);

            // syrk: trailing C -= L21 L21^T, 64x64 tiles, df64 (knuth)
            if (rem > 0) {
                int nb = rem / 64, nt = nb * (nb + 1) / 2;
                float* Ahs = (float*)sh;       // [32][68]
                float* Als = Ahs + 2176;
                float* Bhs = Als + 2176;
                float* Bls = Bhs + 2176;
                const int txc = (tid & 15) * 4;
                const int tyr = (tid >> 4) * 4;
                int o2 = o + 64;
                for (int t = bid; t < nt; t += NBLK) {
                    int bi, bj; tri_map(t, bi, bj);
                    int r0 = o2 + bi * 64, c0 = o2 + bj * 64;
                    float Hh[4][4] = {{0}}, Hl[4][4] = {{0}};
                    for (int kq = 0; kq < 64; kq += 32) {
                        for (int r = warp; r < 64; r += 8) {
                            double va = g_ADA[(size_t)(r0 + r) * NEQ + o + kq + lane];
                            double vb = g_ADA[(size_t)(c0 + r) * NEQ + o + kq + lane];
                            float ha = (float)va, hb = (float)vb;
                            Ahs[lane * 68 + r] = ha;
                            Als[lane * 68 + r] = (float)(va - (double)ha);
                            Bhs[lane * 68 + r] = hb;
                            Bls[lane * 68 + r] = (float)(vb - (double)hb);
                        }
                        __syncthreads();
#pragma unroll 4
                        for (int k = 0; k < 32; k++) {
                            float4 a4 = *(const float4*)(Ahs + k * 68 + tyr);
                            float4 al4 = *(const float4*)(Als + k * 68 + tyr);
                            float4 bh4 = *(const float4*)(Bhs + k * 68 + txc);
                            float4 bl4 = *(const float4*)(Bls + k * 68 + txc);
                            float av[4] = {a4.x, a4.y, a4.z, a4.w};
                            float alv[4] = {al4.x, al4.y, al4.z, al4.w};
                            float bh[4] = {bh4.x, bh4.y, bh4.z, bh4.w};
                            float bl[4] = {bl4.x, bl4.y, bl4.z, bl4.w};
#pragma unroll
                            for (int r = 0; r < 4; r++)
#pragma unroll
                                for (int c = 0; c < 4; c++) {
                                    float p = __fmul_rn(av[r], bh[c]);
                                    float e = __fmaf_rn(av[r], bh[c], -p);
                                    e = __fmaf_rn(av[r], bl[c], e);
                                    e = __fmaf_rn(alv[r], bh[c], e);
                                    float s = __fadd_rn(Hh[r][c], p);
                                    float bb = __fsub_rn(s, Hh[r][c]);
                                    float err = __fadd_rn(__fsub_rn(Hh[r][c], __fsub_rn(s, bb)),
                                                          __fsub_rn(p, bb));
                                    Hh[r][c] = s;
                                    Hl[r][c] = __fadd_rn(Hl[r][c], __fadd_rn(e, err));
                                }
                        }
                        __syncthreads();
                    }
#pragma unroll
                    for (int r = 0; r < 4; r++)
#pragma unroll
                        for (int c = 0; c < 4; c++)
                            g_ADA[(size_t)(r0 + tyr + r) * NEQ + c0 + txc + c] -=
                                ((double)Hh[r][c] + (double)Hl[r][c]);
                }
            }
            gsync(tgt);
        }

        // ---- triangular solves (block 0), reciprocal diag ----
        if (bid == 0) {
            double* S = sh;          // [64][65]
            double* y = sh + 4160;   // [768]
            double* iv = sh + 4928;  // [64]
            for (int i = tid; i < NEQ; i += NTHR) y[i] = g_rhs[i];
            __syncthreads();
            for (int p = 0; p < 12; p++) {
                int o = p * 64;
                for (int i = tid; i < 4096; i += NTHR) {
                    int r = i >> 6, c = i & 63;
                    S[r * 65 + c] = g_ADA[(size_t)(o + r) * NEQ + o + c];
                }
                if (tid < 64) iv[tid] = g_invd[o + tid];
                __syncthreads();
                for (int j = 0; j < 64; j++) {
                    if (tid == 0) y[o + j] *= iv[j];
                    __syncthreads();
                    double yj = y[o + j];
                    if (tid > j && tid < 64) y[o + tid] -= S[tid * 65 + j] * yj;
                    __syncthreads();
                }
                for (int r = o + 64 + warp; r < NEQ; r += 8) {
                    double s = 0.0;
#pragma unroll
                    for (int k = lane; k < 64; k += 32) s += g_ADA[(size_t)r * NEQ + o + k] * y[o + k];
#pragma unroll
                    for (int off = 16; off; off >>= 1) s += __shfl_down_sync(0xffffffffu, s, off);
                    if (lane == 0) y[r] -= s;
                }
                __syncthreads();
            }
            for (int p = 11; p >= 0; p--) {
                int o = p * 64;
                for (int i = tid; i < 4096; i += NTHR) {
                    int r = i >> 6, c = i & 63;
                    S[r * 65 + c] = g_ADA[(size_t)(o + r) * NEQ + o + c];
                }
                if (tid < 64) iv[tid] = g_invd[o + tid];
                __syncthreads();
                for (int j = 63; j >= 0; j--) {
                    if (tid == 0) y[o + j] *= iv[j];
                    __syncthreads();
                    double xj = y[o + j];
                    if (tid < j) y[o + tid] -= S[j * 65 + tid] * xj;
                    __syncthreads();
                }
                for (int i = tid; i < o; i += NTHR) {
                    double s = 0.0;
#pragma unroll 8
                    for (int jj = 0; jj < 64; jj++) s += g_ADA[(size_t)(o + jj) * NEQ + i] * y[o + jj];
                    y[i] -= s;
                }
                __syncthreads();
            }
            for (int i = tid; i < NEQ; i += NTHR) g_dnu[i] = y[i];
        }
        gsync(tgt);

        atmv_phase(sh, 1, bid, tid, warp, lane);
        gsync(tgt);

        if (bid < 16) {
            int i = bid * NTHR + tid;
            double rt = g_rtil[i], t2 = g_t[i], Di = g_Dinv[i];
            double rc = g_rc[i], la = g_lam[i], zz = g_z[i];
            double dz = (rt - t2) * Di;
            double dl = (-rc - la * dz) / zz;
            g_dz[i] = dz; g_dlam[i] = dl;
            double mn = INFINITY;
            if (dz < 0.0) mn = fmin(mn, -zz / dz);
            if (dl < 0.0) mn = fmin(mn, -la / dl);
            blk_min_to(mn, s_red, tid, &s_val);
            if (tid == 0) g_pmin[bid] = s_val;
        }
        gsync(tgt);

        {
            double a = INFINITY;
#pragma unroll
            for (int j = 0; j < 16; j++) a = fmin(a, g_pmin[j]);
            a = fmin(1.0, 0.99 * a);
            if (bid < 16) {
                int i = bid * NTHR + tid;
                g_z[i]   += a * g_dz[i];
                g_lam[i] += a * g_dlam[i];
            } else if (bid < 19) {
                int i = (bid - 16) * NTHR + tid;
                if (i < NEQ) g_nu[i] += a * g_dnu[i];
            }
        }
        gsync(tgt);
    }

    if (bid < 16) {
        int i = bid * NTHR + tid;
        out[i] = (float)g_z[i];
    }
}

// ---------------- host launcher (2 graph nodes) ----------------
extern "C" void kernel_launch(void* const* d_in, const int* in_sizes, int n_in,
                              void* d_out, int out_size) {
    const float* puz  = (const float*)d_in[0];
    const void*  Araw = d_in[1];
    const float* logz = (const float*)d_in[2];
    float* out = (float*)d_out;

    static int attr_set = 0;
    if (!attr_set) {
        cudaFuncSetAttribute(k_main, cudaFuncAttributeMaxDynamicSharedMemorySize,
                             SMEM_DBL * (int)sizeof(double));
        attr_set = 1;
    }

    k_reset<<<1, 1>>>();
    k_main<<<NBLK, NTHR, SMEM_DBL * sizeof(double)>>>(puz, Araw, logz, out);
}

// round 13
// speedup vs baseline: 3.9780x; 1.1958x over previous
#include <cuda_runtime.h>
#include <math.h>

#define NX    4096
#define NEQ   768
#define MU    0.1
#define SIG   0.1
#define ITERS 40
#define NBLK  132
#define NTHR  256
#define SMEM_DBL 8320          // 66560 bytes dynamic shared

// ---------------- device-global state ----------------
__device__ double g_A[(size_t)NEQ * NX];
__device__ double g_AT[(size_t)NX * NEQ];
__device__ float  g_Ah[(size_t)NEQ * NX];
__device__ float  g_Al[(size_t)NEQ * NX];
__device__ float  g_Bh[(size_t)NEQ * NX];   // (A * Dinv) rounded to fp32
__device__ double g_q[NX];
__device__ double g_b[NEQ];
__device__ double g_z[NX];
__device__ double g_lam[NX];
__device__ double g_nu[NEQ];
__device__ double g_t[NX];
__device__ double g_rc[NX];
__device__ double g_Dinv[NX];
__device__ double g_rtil[NX];
__device__ double g_w[NX];
__device__ double g_dnu[NEQ];
__device__ double g_rhs[NEQ];
__device__ double g_ADA[NEQ * NEQ];
__device__ double g_invd[NEQ];       // 1/L[j][j] per factored column
__device__ double g_dz[NX];
__device__ double g_dlam[NX];
__device__ double g_part[16];
__device__ double g_pmin[16];
__device__ int    g_is64;
__device__ unsigned g_count;

__global__ void k_reset() { g_count = 0u; }

// software grid barrier: arrive with atomic, poll with plain L2 load
__device__ __forceinline__ void gsync(unsigned &tgt) {
    __syncthreads();
    if (threadIdx.x == 0) {
        __threadfence();
        atomicAdd(&g_count, 1u);
        tgt += NBLK;
        while (*(volatile unsigned*)&g_count < tgt) __nanosleep(32);
        __threadfence();
    }
    __syncthreads();
}

__device__ __forceinline__ void blk_sum_to(double v, double* s_red, int tid, double* dst) {
#pragma unroll
    for (int off = 16; off; off >>= 1) v += __shfl_down_sync(0xffffffffu, v, off);
    if ((tid & 31) == 0) s_red[tid >> 5] = v;
    __syncthreads();
    if (tid == 0) { double r = 0; for (int w = 0; w < 8; w++) r += s_red[w]; *dst = r; }
    __syncthreads();
}
__device__ __forceinline__ void blk_min_to(double v, double* s_red, int tid, double* dst) {
#pragma unroll
    for (int off = 16; off; off >>= 1) v = fmin(v, __shfl_down_sync(0xffffffffu, v, off));
    if ((tid & 31) == 0) s_red[tid >> 5] = v;
    __syncthreads();
    if (tid == 0) { double r = s_red[0]; for (int w = 1; w < 8; w++) r = fmin(r, s_red[w]); *dst = r; }
    __syncthreads();
}

__device__ __forceinline__ void tri_map(int t, int &bi, int &bj) {
    int b = 0;
    while ((b + 1) * (b + 2) / 2 <= t) b++;
    bi = b; bj = t - b * (b + 1) / 2;
}

// range-safe fp64 reciprocal: integer magic seed + 4 fused Newton steps
__device__ __forceinline__ double fast_rcp(double d) {
    double r = __longlong_as_double(0x7FDE6238502484BAll - __double_as_longlong(d));
#pragma unroll
    for (int s = 0; s < 4; s++) {
        double e = __fma_rn(-d, r, 1.0);
        r = __fma_rn(r, e, r);
    }
    return r;
}

// A @ w  (mode 0 -> g_b ; mode 1 -> g_rhs = A@w - b)
__device__ __forceinline__ void amv_phase(double* sv, int mode, int bid, int tid, int warp, int lane) {
    for (int i = tid; i < NX; i += NTHR) sv[i] = g_w[i];
    __syncthreads();
    int row = bid * 8 + warp;
    if (row < NEQ) {
        const double* ar = g_A + (size_t)row * NX;
        double s = 0.0;
        for (int k = lane; k < NX; k += 32) s += ar[k] * sv[k];
#pragma unroll
        for (int off = 16; off; off >>= 1) s += __shfl_down_sync(0xffffffffu, s, off);
        if (lane == 0) { if (mode == 0) g_b[row] = s; else g_rhs[row] = s - g_b[row]; }
    }
    __syncthreads();
}

// g_t = A^T @ (mode ? dnu : nu)
__device__ __forceinline__ void atmv_phase(double* sx, int mode, int bid, int tid, int warp, int lane) {
    const double* x = mode ? g_dnu : g_nu;
    for (int i = tid; i < NEQ; i += NTHR) sx[i] = x[i];
    __syncthreads();
    for (int j = bid * 8 + warp; j < NX; j += NBLK * 8) {
        const double* ar = g_AT + (size_t)j * NEQ;
        double s = 0.0;
        for (int e = lane; e < NEQ; e += 32) s += ar[e] * sx[e];
#pragma unroll
        for (int off = 16; off; off >>= 1) s += __shfl_down_sync(0xffffffffu, s, off);
        if (lane == 0) g_t[j] = s;
    }
    __syncthreads();
}

__global__ void __launch_bounds__(NTHR, 1)
k_main(const float* __restrict__ puz, const void* __restrict__ Araw,
       const float* __restrict__ logz, float* __restrict__ out) {
    extern __shared__ double sh[];
    __shared__ double s_red[32];
    __shared__ double s_val;
    __shared__ int s_cnt;
    const int tid = threadIdx.x, bid = blockIdx.x;
    const int warp = tid >> 5, lane = tid & 31;
    unsigned tgt = 0;

    // ---- dtype detect (block 0 reads first 16KB only)
    if (bid == 0) {
        if (tid == 0) s_cnt = 0;
        __syncthreads();
        int c = 0;
        const unsigned* W = (const unsigned*)Araw;
        for (int i = tid; i < 4096; i += NTHR) {
            float v = __uint_as_float(W[i]);
            if (v >= 1.0f && v < 4.0f) c++;
        }
        atomicAdd(&s_cnt, c);
        __syncthreads();
        if (tid == 0) g_is64 = (s_cnt > 64) ? 1 : 0;
    }
    gsync(tgt);

    // ---- widen A + split + init state
    {
        int is64 = g_is64;
        const double* Ad = (const double*)Araw;
        const float*  Af = (const float*)Araw;
        for (size_t i = (size_t)bid * NTHR + tid; i < (size_t)NEQ * NX; i += (size_t)NBLK * NTHR) {
            double v = is64 ? Ad[i] : (double)Af[i];
            g_A[i] = v;
            float h = (float)v;
            g_Ah[i] = h;
            g_Al[i] = (float)(v - (double)h);
        }
        int i = bid * NTHR + tid;
        if (i < NX) {
            g_q[i] = -(double)puz[i];
            g_z[i] = 1.0; g_lam[i] = 1.0;
            g_w[i] = exp((double)logz[i]);
        }
        if (i < NEQ) g_nu[i] = 0.0;
    }
    gsync(tgt);

    // ---- transpose A -> g_AT
    {
        int tx = tid & 31, ty = tid >> 5;
        for (int t = bid; t < (NX / 32) * (NEQ / 32); t += NBLK) {
            int j0 = (t % (NX / 32)) * 32, e0 = (t / (NX / 32)) * 32;
#pragma unroll
            for (int m = 0; m < 4; m++) {
                int e = e0 + ty + 8 * m;
                sh[(ty + 8 * m) * 33 + tx] = g_A[(size_t)e * NX + j0 + tx];
            }
            __syncthreads();
#pragma unroll
            for (int m = 0; m < 4; m++) {
                int j = j0 + ty + 8 * m;
                g_AT[(size_t)j * NEQ + e0 + tx] = sh[tx * 33 + ty + 8 * m];
            }
            __syncthreads();
        }
    }
    gsync(tgt);

    // ---- b = A @ exp(log_z0)
    amv_phase(sh, 0, bid, tid, warp, lane);
    gsync(tgt);

    // =================== IPM loop ===================
    for (int it = 0; it < ITERS; it++) {
        atmv_phase(sh, 0, bid, tid, warp, lane);
        gsync(tgt);

        if (bid < 16) {
            int i = bid * NTHR + tid;
            blk_sum_to(g_z[i] * g_lam[i], s_red, tid, &s_val);
            if (tid == 0) g_part[bid] = s_val;
        }
        gsync(tgt);

        if (bid < 16) {
            double gap = 0;
#pragma unroll
            for (int j = 0; j < 16; j++) gap += g_part[j];
            gap /= (double)NX;
            int i = bid * NTHR + tid;
            double z = g_z[i], la = g_lam[i];
            double rd = MU * z + g_q[i] - la + g_t[i];
            double rc = z * la - SIG * gap;
            double Di = 1.0 / (MU + la / z);
            double rt = -rd - rc / z;
            g_rc[i] = rc; g_Dinv[i] = Di; g_rtil[i] = rt;
            g_w[i] = rt * Di + z;
        }
        gsync(tgt);

        // rhs = A@w - b ; B = fp32( A*diag(Dinv) )
        amv_phase(sh, 1, bid, tid, warp, lane);
        for (size_t i = (size_t)bid * NTHR + tid; i < (size_t)NEQ * NX; i += (size_t)NBLK * NTHR) {
            int k = (int)(i & (NX - 1));
            g_Bh[i] = (float)(g_A[i] * g_Dinv[k]);
        }
        gsync(tgt);

        // ---- Gram: ADA = A D A^T, 64x64 tiles
        // plain fp32 FFMA over 16-term chunks, folded exactly (Fast2Sum) into
        // an fp32 (hi,lo) pair. Products are exact inside FFMA; terms are
        // positive (A = rand, Dinv > 0) so the compensated pair carries the
        // sum to ~1e-9 relative.
        {
            const int is64 = g_is64;
            float* Ahs = (float*)sh;         // [32][68]
            float* Als = Ahs + 2176;         // is64 only
            float* Bhs = Als + 2176;
            const int txc = (tid & 15) * 4;
            const int tyr = (tid >> 4) * 4;
            for (int t = bid; t < 78; t += NBLK) {
                int bi, bj; tri_map(t, bi, bj);
                int row0 = bi * 64, col0 = bj * 64;
                float Sh_[4][4] = {{0}}, Sl_[4][4] = {{0}};
                for (int k0 = 0; k0 < NX; k0 += 32) {
                    for (int r = warp; r < 64; r += 8) {
                        size_t ga = (size_t)(row0 + r) * NX + k0 + lane;
                        size_t gb = (size_t)(col0 + r) * NX + k0 + lane;
                        Ahs[lane * 68 + r] = g_Ah[ga];
                        if (is64) Als[lane * 68 + r] = g_Al[ga];
                        Bhs[lane * 68 + r] = g_Bh[gb];
                    }
                    __syncthreads();
                    if (!is64) {
#pragma unroll
                        for (int half = 0; half < 2; half++) {
                            float acc[4][4] = {{0}};
#pragma unroll
                            for (int kk = 0; kk < 16; kk++) {
                                int k = half * 16 + kk;
                                float4 a4 = *(const float4*)(Ahs + k * 68 + tyr);
                                float4 b4 = *(const float4*)(Bhs + k * 68 + txc);
                                float av[4] = {a4.x, a4.y, a4.z, a4.w};
                                float bv[4] = {b4.x, b4.y, b4.z, b4.w};
#pragma unroll
                                for (int r = 0; r < 4; r++)
#pragma unroll
                                    for (int c = 0; c < 4; c++)
                                        acc[r][c] = __fmaf_rn(av[r], bv[c], acc[r][c]);
                            }
                            // exact Fast2Sum fold: |Sh| >= |acc| (positive sums)
#pragma unroll
                            for (int r = 0; r < 4; r++)
#pragma unroll
                                for (int c = 0; c < 4; c++) {
                                    float ts = __fadd_rn(Sh_[r][c], acc[r][c]);
                                    float e  = __fadd_rn(__fsub_rn(Sh_[r][c], ts), acc[r][c]);
                                    Sh_[r][c] = ts;
                                    Sl_[r][c] = __fadd_rn(Sl_[r][c], e);
                                }
                        }
                    } else {
#pragma unroll
                        for (int half = 0; half < 2; half++) {
                            float acc[4][4] = {{0}};
                            float accl[4][4] = {{0}};
#pragma unroll
                            for (int kk = 0; kk < 16; kk++) {
                                int k = half * 16 + kk;
                                float4 a4 = *(const float4*)(Ahs + k * 68 + tyr);
                                float4 al4 = *(const float4*)(Als + k * 68 + tyr);
                                float4 b4 = *(const float4*)(Bhs + k * 68 + txc);
                                float av[4] = {a4.x, a4.y, a4.z, a4.w};
                                float alv[4] = {al4.x, al4.y, al4.z, al4.w};
                                float bv[4] = {b4.x, b4.y, b4.z, b4.w};
#pragma unroll
                                for (int r = 0; r < 4; r++)
#pragma unroll
                                    for (int c = 0; c < 4; c++) {
                                        acc[r][c]  = __fmaf_rn(av[r],  bv[c], acc[r][c]);
                                        accl[r][c] = __fmaf_rn(alv[r], bv[c], accl[r][c]);
                                    }
                            }
#pragma unroll
                            for (int r = 0; r < 4; r++)
#pragma unroll
                                for (int c = 0; c < 4; c++) {
                                    float ts = __fadd_rn(Sh_[r][c], acc[r][c]);
                                    float e  = __fadd_rn(__fsub_rn(Sh_[r][c], ts), acc[r][c]);
                                    Sh_[r][c] = ts;
                                    Sl_[r][c] = __fadd_rn(Sl_[r][c], __fadd_rn(e, accl[r][c]));
                                }
                        }
                    }
                    __syncthreads();
                }
#pragma unroll
                for (int r = 0; r < 4; r++)
#pragma unroll
                    for (int c = 0; c < 4; c++)
                        g_ADA[(size_t)(row0 + tyr + r) * NEQ + col0 + txc + c] =
                            (double)Sh_[r][c] + (double)Sl_[r][c];
            }
        }
        gsync(tgt);

        // ---- Cholesky: 12 panels of 64 ----
        for (int p = 0; p < 12; p++) {
            int o = p * 64, rem = NEQ - o - 64;

            // potrf (block 0): LDL^T-style rank-1 with range-safe Newton reciprocal
            if (bid == 0) {
                double* S   = sh;            // [64][65]
                double* wv  = sh + 4160;     // [64]
                double* inv = sh + 4224;     // [64]
                double* rsv = sh + 4288;     // [64]
                for (int i = tid; i < 4096; i += NTHR) {
                    int r = i >> 6, c = i & 63;
                    S[r * 65 + c] = g_ADA[(size_t)(o + r) * NEQ + o + c];
                }
                __syncthreads();
                int r = tid & 63, q = tid >> 6;
                for (int j = 0; j < 64; j++) {
                    if (q == 0) {
                        double d = fmax(S[j * 65 + j], 1e-300);
                        double ri = fast_rcp(d);
                        if (r == j) inv[j] = ri;
                        if (r > j) wv[r] = S[r * 65 + j] * ri;
                    }
                    __syncthreads();
                    if (r > j) {
                        double wr = wv[r];
                        for (int c = j + 1 + q; c <= r; c += 4)
                            S[r * 65 + c] -= wr * S[c * 65 + j];
                    }
                    __syncthreads();
                }
                if (tid < 64) {
                    double rs = sqrt(inv[tid]);
                    rsv[tid] = rs;
                    g_invd[o + tid] = rs;
                }
                __syncthreads();
                for (int i = tid; i < 4096; i += NTHR) {
                    int rr = i >> 6, c = i & 63;
                    g_ADA[(size_t)(o + rr) * NEQ + o + c] = S[rr * 65 + c] * rsv[c];
                }
            }
            gsync(tgt);

            // trsm: column-sweep, reciprocal diag from g_invd
            if (rem > 0 && bid < rem / 64) {
                double* L = sh;          // [64][65]
                double* X = sh + 4160;   // [64][65]
                int base = o + 64 + bid * 64;
                for (int i = tid; i < 4096; i += NTHR) {
                    int r = i >> 6, c = i & 63;
                    L[r * 65 + c] = g_ADA[(size_t)(o + r) * NEQ + o + c];
                    X[r * 65 + c] = g_ADA[(size_t)(base + r) * NEQ + o + c];
                }
                __syncthreads();   // REQUIRED before diag overwrite (cross-thread)
                if (tid < 64) L[tid * 65 + tid] = g_invd[o + tid];
                __syncthreads();
                int r = tid & 63, q = tid >> 6;
                for (int j = 0; j < 64; j++) {
                    if (q == 0) X[r * 65 + j] *= L[j * 65 + j];
                    __syncthreads();
                    double xj = X[r * 65 + j];
                    for (int c = j + 1 + q; c < 64; c += 4)
                        X[r * 65 + c] -= xj * L[c * 65 + j];
                    __syncthreads();
                }
                for (int i = tid; i < 4096; i += NTHR) {
                    int rr = i >> 6, c = i & 63;
                    g_ADA[(size_t)(base + rr) * NEQ + o + c] = X[rr * 65 + c];
                }
            }
            gsync(tgt);

            // syrk: trailing C -= L21 L21^T, 64x64 tiles, df64 (knuth, validated)
            if (rem > 0) {
                int nb = rem / 64, nt = nb * (nb + 1) / 2;
                float* Ahs = (float*)sh;       // [32][68]
                float* Als = Ahs + 2176;
                float* Bhs = Als + 2176;
                float* Bls = Bhs + 2176;
                const int txc = (tid & 15) * 4;
                const int tyr = (tid >> 4) * 4;
                int o2 = o + 64;
                for (int t = bid; t < nt; t += NBLK) {
                    int bi, bj; tri_map(t, bi, bj);
                    int r0 = o2 + bi * 64, c0 = o2 + bj * 64;
                    float Hh[4][4] = {{0}}, Hl[4][4] = {{0}};
                    for (int kq = 0; kq < 64; kq += 32) {
                        for (int r = warp; r < 64; r += 8) {
                            double va = g_ADA[(size_t)(r0 + r) * NEQ + o + kq + lane];
                            double vb = g_ADA[(size_t)(c0 + r) * NEQ + o + kq + lane];
                            float ha = (float)va, hb = (float)vb;
                            Ahs[lane * 68 + r] = ha;
                            Als[lane * 68 + r] = (float)(va - (double)ha);
                            Bhs[lane * 68 + r] = hb;
                            Bls[lane * 68 + r] = (float)(vb - (double)hb);
                        }
                        __syncthreads();
#pragma unroll 4
                        for (int k = 0; k < 32; k++) {
                            float4 a4 = *(const float4*)(Ahs + k * 68 + tyr);
                            float4 al4 = *(const float4*)(Als + k * 68 + tyr);
                            float4 bh4 = *(const float4*)(Bhs + k * 68 + txc);
                            float4 bl4 = *(const float4*)(Bls + k * 68 + txc);
                            float av[4] = {a4.x, a4.y, a4.z, a4.w};
                            float alv[4] = {al4.x, al4.y, al4.z, al4.w};
                            float bh[4] = {bh4.x, bh4.y, bh4.z, bh4.w};
                            float bl[4] = {bl4.x, bl4.y, bl4.z, bl4.w};
#pragma unroll
                            for (int r = 0; r < 4; r++)
#pragma unroll
                                for (int c = 0; c < 4; c++) {
                                    float p = __fmul_rn(av[r], bh[c]);
                                    float e = __fmaf_rn(av[r], bh[c], -p);
                                    e = __fmaf_rn(av[r], bl[c], e);
                                    e = __fmaf_rn(alv[r], bh[c], e);
                                    float s = __fadd_rn(Hh[r][c], p);
                                    float bb = __fsub_rn(s, Hh[r][c]);
                                    float err = __fadd_rn(__fsub_rn(Hh[r][c], __fsub_rn(s, bb)),
                                                          __fsub_rn(p, bb));
                                    Hh[r][c] = s;
                                    Hl[r][c] = __fadd_rn(Hl[r][c], __fadd_rn(e, err));
                                }
                        }
                        __syncthreads();
                    }
#pragma unroll
                    for (int r = 0; r < 4; r++)
#pragma unroll
                        for (int c = 0; c < 4; c++)
                            g_ADA[(size_t)(r0 + tyr + r) * NEQ + c0 + txc + c] -=
                                ((double)Hh[r][c] + (double)Hl[r][c]);
                }
            }
            gsync(tgt);
        }

        // ---- triangular solves (block 0), reciprocal diag ----
        if (bid == 0) {
            double* S = sh;          // [64][65]
            double* y = sh + 4160;   // [768]
            double* iv = sh + 4928;  // [64]
            for (int i = tid; i < NEQ; i += NTHR) y[i] = g_rhs[i];
            __syncthreads();
            for (int p = 0; p < 12; p++) {
                int o = p * 64;
                for (int i = tid; i < 4096; i += NTHR) {
                    int r = i >> 6, c = i & 63;
                    S[r * 65 + c] = g_ADA[(size_t)(o + r) * NEQ + o + c];
                }
                if (tid < 64) iv[tid] = g_invd[o + tid];
                __syncthreads();
                for (int j = 0; j < 64; j++) {
                    if (tid == 0) y[o + j] *= iv[j];
                    __syncthreads();
                    double yj = y[o + j];
                    if (tid > j && tid < 64) y[o + tid] -= S[tid * 65 + j] * yj;
                    __syncthreads();
                }
                for (int r = o + 64 + warp; r < NEQ; r += 8) {
                    double s = 0.0;
#pragma unroll
                    for (int k = lane; k < 64; k += 32) s += g_ADA[(size_t)r * NEQ + o + k] * y[o + k];
#pragma unroll
                    for (int off = 16; off; off >>= 1) s += __shfl_down_sync(0xffffffffu, s, off);
                    if (lane == 0) y[r] -= s;
                }
                __syncthreads();
            }
            for (int p = 11; p >= 0; p--) {
                int o = p * 64;
                for (int i = tid; i < 4096; i += NTHR) {
                    int r = i >> 6, c = i & 63;
                    S[r * 65 + c] = g_ADA[(size_t)(o + r) * NEQ + o + c];
                }
                if (tid < 64) iv[tid] = g_invd[o + tid];
                __syncthreads();
                for (int j = 63; j >= 0; j--) {
                    if (tid == 0) y[o + j] *= iv[j];
                    __syncthreads();
                    double xj = y[o + j];
                    if (tid < j) y[o + tid] -= S[j * 65 + tid] * xj;
                    __syncthreads();
                }
                for (int i = tid; i < o; i += NTHR) {
                    double s = 0.0;
#pragma unroll 8
                    for (int jj = 0; jj < 64; jj++) s += g_ADA[(size_t)(o + jj) * NEQ + i] * y[o + jj];
                    y[i] -= s;
                }
                __syncthreads();
            }
            for (int i = tid; i < NEQ; i += NTHR) g_dnu[i] = y[i];
        }
        gsync(tgt);

        atmv_phase(sh, 1, bid, tid, warp, lane);
        gsync(tgt);

        if (bid < 16) {
            int i = bid * NTHR + tid;
            double rt = g_rtil[i], t2 = g_t[i], Di = g_Dinv[i];
            double rc = g_rc[i], la = g_lam[i], zz = g_z[i];
            double dz = (rt - t2) * Di;
            double dl = (-rc - la * dz) / zz;
            g_dz[i] = dz; g_dlam[i] = dl;
            double mn = INFINITY;
            if (dz < 0.0) mn = fmin(mn, -zz / dz);
            if (dl < 0.0) mn = fmin(mn, -la / dl);
            blk_min_to(mn, s_red, tid, &s_val);
            if (tid == 0) g_pmin[bid] = s_val;
        }
        gsync(tgt);

        {
            double a = INFINITY;
#pragma unroll
            for (int j = 0; j < 16; j++) a = fmin(a, g_pmin[j]);
            a = fmin(1.0, 0.99 * a);
            if (bid < 16) {
                int i = bid * NTHR + tid;
                g_z[i]   += a * g_dz[i];
                g_lam[i] += a * g_dlam[i];
            } else if (bid < 19) {
                int i = (bid - 16) * NTHR + tid;
                if (i < NEQ) g_nu[i] += a * g_dnu[i];
            }
        }
        gsync(tgt);
    }

    if (bid < 16) {
        int i = bid * NTHR + tid;
        out[i] = (float)g_z[i];
    }
}

// ---------------- host launcher (2 graph nodes) ----------------
extern "C" void kernel_launch(void* const* d_in, const int* in_sizes, int n_in,
                              void* d_out, int out_size) {
    const float* puz  = (const float*)d_in[0];
    const void*  Araw = d_in[1];
    const float* logz = (const float*)d_in[2];
    float* out = (float*)d_out;

    static int attr_set = 0;
    if (!attr_set) {
        cudaFuncSetAttribute(k_main, cudaFuncAttributeMaxDynamicSharedMemorySize,
                             SMEM_DBL * (int)sizeof(double));
        attr_set = 1;
    }

    k_reset<<<1, 1>>>();
    k_main<<<NBLK, NTHR, SMEM_DBL * sizeof(double)>>>(puz, Araw, logz, out);
}

// round 15
// speedup vs baseline: 4.5647x; 1.1475x over previous
#include <cuda_runtime.h>
#include <math.h>

#define NX    4096
#define NEQ   768
#define MU    0.1
#define SIG   0.1
#define ITERS 40
#define NBLK  132
#define NTHR  256
#define SMEM_DBL 8320          // 66560 bytes dynamic shared

// ---------------- device-global state ----------------
__device__ double g_A[(size_t)NEQ * NX];
__device__ double g_AT[(size_t)NX * NEQ];
__device__ float  g_Ah[(size_t)NEQ * NX];
__device__ float  g_Al[(size_t)NEQ * NX];
__device__ float  g_Bh[(size_t)NEQ * NX];   // (A * Dinv) rounded to fp32
__device__ double g_q[NX];
__device__ double g_b[NEQ];
__device__ double g_z[NX];
__device__ double g_lam[NX];
__device__ double g_nu[NEQ];
__device__ double g_t[NX];
__device__ double g_rc[NX];
__device__ double g_Dinv[NX];
__device__ double g_rtil[NX];
__device__ double g_w[NX];
__device__ double g_dnu[NEQ];
__device__ double g_rhs[NEQ];
__device__ double g_ADA[NEQ * NEQ];
__device__ double g_invd[NEQ];           // 1/L[j][j]
__device__ double g_W[12 * 64 * 64];     // M_p = inv(L_pp)^T, row-major 64x64 per panel
__device__ double g_dz[NX];
__device__ double g_dlam[NX];
__device__ double g_part[16];
__device__ double g_pmin[16];
__device__ int    g_is64;
__device__ unsigned g_count;

__global__ void k_reset() { g_count = 0u; }

// software grid barrier: arrive with atomic, poll with plain L2 load
__device__ __forceinline__ void gsync(unsigned &tgt) {
    __syncthreads();
    if (threadIdx.x == 0) {
        __threadfence();
        atomicAdd(&g_count, 1u);
        tgt += NBLK;
        while (*(volatile unsigned*)&g_count < tgt) __nanosleep(32);
        __threadfence();
    }
    __syncthreads();
}

__device__ __forceinline__ void blk_sum_to(double v, double* s_red, int tid, double* dst) {
#pragma unroll
    for (int off = 16; off; off >>= 1) v += __shfl_down_sync(0xffffffffu, v, off);
    if ((tid & 31) == 0) s_red[tid >> 5] = v;
    __syncthreads();
    if (tid == 0) { double r = 0; for (int w = 0; w < 8; w++) r += s_red[w]; *dst = r; }
    __syncthreads();
}
__device__ __forceinline__ void blk_min_to(double v, double* s_red, int tid, double* dst) {
#pragma unroll
    for (int off = 16; off; off >>= 1) v = fmin(v, __shfl_down_sync(0xffffffffu, v, off));
    if ((tid & 31) == 0) s_red[tid >> 5] = v;
    __syncthreads();
    if (tid == 0) { double r = s_red[0]; for (int w = 1; w < 8; w++) r = fmin(r, s_red[w]); *dst = r; }
    __syncthreads();
}

__device__ __forceinline__ void tri_map(int t, int &bi, int &bj) {
    int b = 0;
    while ((b + 1) * (b + 2) / 2 <= t) b++;
    bi = b; bj = t - b * (b + 1) / 2;
}

// range-safe fp64 reciprocal: integer magic seed + 4 fused Newton steps
__device__ __forceinline__ double fast_rcp(double d) {
    double r = __longlong_as_double(0x7FDE6238502484BAll - __double_as_longlong(d));
#pragma unroll
    for (int s = 0; s < 4; s++) {
        double e = __fma_rn(-d, r, 1.0);
        r = __fma_rn(r, e, r);
    }
    return r;
}

// potrf of 64x64 diagonal block at offset o (run by ONE block, 256 threads).
// LDL^T-style rank-1 with Newton reciprocal; deferred column scaling.
// Writes L to g_ADA and 1/L[j][j] to g_invd. Uses sh[0..4352).
__device__ void potrf_panel(double* sh, int o, int tid) {
    double* S   = sh;            // [64][65]
    double* wv  = sh + 4160;     // [64]
    double* inv = sh + 4224;     // [64]
    double* rsv = sh + 4288;     // [64]
    for (int i = tid; i < 4096; i += NTHR) {
        int r = i >> 6, c = i & 63;
        S[r * 65 + c] = g_ADA[(size_t)(o + r) * NEQ + o + c];
    }
    __syncthreads();
    int r = tid & 63, q = tid >> 6;
    for (int j = 0; j < 64; j++) {
        if (q == 0) {
            double d = fmax(S[j * 65 + j], 1e-300);
            double ri = fast_rcp(d);
            if (r == j) inv[j] = ri;
            if (r > j) wv[r] = S[r * 65 + j] * ri;
        }
        __syncthreads();
        if (r > j) {
            double wr = wv[r];
            for (int c = j + 1 + q; c <= r; c += 4)
                S[r * 65 + c] -= wr * S[c * 65 + j];
        }
        __syncthreads();
    }
    if (tid < 64) {
        double rs = sqrt(inv[tid]);
        rsv[tid] = rs;
        g_invd[o + tid] = rs;
    }
    __syncthreads();
    for (int i = tid; i < 4096; i += NTHR) {
        int rr = i >> 6, c = i & 63;
        g_ADA[(size_t)(o + rr) * NEQ + o + c] = S[rr * 65 + c] * rsv[c];
    }
}

// A @ w  (mode 0 -> g_b ; mode 1 -> g_rhs = A@w - b)
__device__ __forceinline__ void amv_phase(double* sv, int mode, int bid, int tid, int warp, int lane) {
    for (int i = tid; i < NX; i += NTHR) sv[i] = g_w[i];
    __syncthreads();
    int row = bid * 8 + warp;
    if (row < NEQ) {
        const double* ar = g_A + (size_t)row * NX;
        double s = 0.0;
        for (int k = lane; k < NX; k += 32) s += ar[k] * sv[k];
#pragma unroll
        for (int off = 16; off; off >>= 1) s += __shfl_down_sync(0xffffffffu, s, off);
        if (lane == 0) { if (mode == 0) g_b[row] = s; else g_rhs[row] = s - g_b[row]; }
    }
    __syncthreads();
}

// g_t = A^T @ (mode ? dnu : nu)
__device__ __forceinline__ void atmv_phase(double* sx, int mode, int bid, int tid, int warp, int lane) {
    const double* x = mode ? g_dnu : g_nu;
    for (int i = tid; i < NEQ; i += NTHR) sx[i] = x[i];
    __syncthreads();
    for (int j = bid * 8 + warp; j < NX; j += NBLK * 8) {
        const double* ar = g_AT + (size_t)j * NEQ;
        double s = 0.0;
        for (int e = lane; e < NEQ; e += 32) s += ar[e] * sx[e];
#pragma unroll
        for (int off = 16; off; off >>= 1) s += __shfl_down_sync(0xffffffffu, s, off);
        if (lane == 0) g_t[j] = s;
    }
    __syncthreads();
}

__global__ void __launch_bounds__(NTHR, 1)
k_main(const float* __restrict__ puz, const void* __restrict__ Araw,
       const float* __restrict__ logz, float* __restrict__ out) {
    extern __shared__ double sh[];
    __shared__ double s_red[32];
    __shared__ double s_val;
    __shared__ int s_cnt;
    const int tid = threadIdx.x, bid = blockIdx.x;
    const int warp = tid >> 5, lane = tid & 31;
    unsigned tgt = 0;

    // ---- dtype detect (block 0 reads first 16KB only)
    if (bid == 0) {
        if (tid == 0) s_cnt = 0;
        __syncthreads();
        int c = 0;
        const unsigned* W = (const unsigned*)Araw;
        for (int i = tid; i < 4096; i += NTHR) {
            float v = __uint_as_float(W[i]);
            if (v >= 1.0f && v < 4.0f) c++;
        }
        atomicAdd(&s_cnt, c);
        __syncthreads();
        if (tid == 0) g_is64 = (s_cnt > 64) ? 1 : 0;
    }
    gsync(tgt);

    // ---- widen A + split + init state
    {
        int is64 = g_is64;
        const double* Ad = (const double*)Araw;
        const float*  Af = (const float*)Araw;
        for (size_t i = (size_t)bid * NTHR + tid; i < (size_t)NEQ * NX; i += (size_t)NBLK * NTHR) {
            double v = is64 ? Ad[i] : (double)Af[i];
            g_A[i] = v;
            float h = (float)v;
            g_Ah[i] = h;
            g_Al[i] = (float)(v - (double)h);
        }
        int i = bid * NTHR + tid;
        if (i < NX) {
            g_q[i] = -(double)puz[i];
            g_z[i] = 1.0; g_lam[i] = 1.0;
            g_w[i] = exp((double)logz[i]);
        }
        if (i < NEQ) g_nu[i] = 0.0;
    }
    gsync(tgt);

    // ---- transpose A -> g_AT
    {
        int tx = tid & 31, ty = tid >> 5;
        for (int t = bid; t < (NX / 32) * (NEQ / 32); t += NBLK) {
            int j0 = (t % (NX / 32)) * 32, e0 = (t / (NX / 32)) * 32;
#pragma unroll
            for (int m = 0; m < 4; m++) {
                int e = e0 + ty + 8 * m;
                sh[(ty + 8 * m) * 33 + tx] = g_A[(size_t)e * NX + j0 + tx];
            }
            __syncthreads();
#pragma unroll
            for (int m = 0; m < 4; m++) {
                int j = j0 + ty + 8 * m;
                g_AT[(size_t)j * NEQ + e0 + tx] = sh[tx * 33 + ty + 8 * m];
            }
            __syncthreads();
        }
    }
    gsync(tgt);

    // ---- b = A @ exp(log_z0)
    amv_phase(sh, 0, bid, tid, warp, lane);
    gsync(tgt);

    // =================== IPM loop ===================
    for (int it = 0; it < ITERS; it++) {
        atmv_phase(sh, 0, bid, tid, warp, lane);
        gsync(tgt);

        if (bid < 16) {
            int i = bid * NTHR + tid;
            blk_sum_to(g_z[i] * g_lam[i], s_red, tid, &s_val);
            if (tid == 0) g_part[bid] = s_val;
        }
        gsync(tgt);

        if (bid < 16) {
            double gap = 0;
#pragma unroll
            for (int j = 0; j < 16; j++) gap += g_part[j];
            gap /= (double)NX;
            int i = bid * NTHR + tid;
            double z = g_z[i], la = g_lam[i];
            double rd = MU * z + g_q[i] - la + g_t[i];
            double rc = z * la - SIG * gap;
            double Di = 1.0 / (MU + la / z);
            double rt = -rd - rc / z;
            g_rc[i] = rc; g_Dinv[i] = Di; g_rtil[i] = rt;
            g_w[i] = rt * Di + z;
        }
        gsync(tgt);

        // rhs = A@w - b ; B = fp32( A*diag(Dinv) )
        amv_phase(sh, 1, bid, tid, warp, lane);
        for (size_t i = (size_t)bid * NTHR + tid; i < (size_t)NEQ * NX; i += (size_t)NBLK * NTHR) {
            int k = (int)(i & (NX - 1));
            g_Bh[i] = (float)(g_A[i] * g_Dinv[k]);
        }
        gsync(tgt);

        // ---- Gram: ADA = A D A^T, 64x64 tiles; block 0 then does potrf panel 0
        {
            const int is64 = g_is64;
            float* Ahs = (float*)sh;         // [32][68]
            float* Als = Ahs + 2176;         // is64 only
            float* Bhs = Als + 2176;
            const int txc = (tid & 15) * 4;
            const int tyr = (tid >> 4) * 4;
            for (int t = bid; t < 78; t += NBLK) {
                int bi, bj; tri_map(t, bi, bj);
                int row0 = bi * 64, col0 = bj * 64;
                float Sh_[4][4] = {{0}}, Sl_[4][4] = {{0}};
                for (int k0 = 0; k0 < NX; k0 += 32) {
                    for (int r = warp; r < 64; r += 8) {
                        size_t ga = (size_t)(row0 + r) * NX + k0 + lane;
                        size_t gb = (size_t)(col0 + r) * NX + k0 + lane;
                        Ahs[lane * 68 + r] = g_Ah[ga];
                        if (is64) Als[lane * 68 + r] = g_Al[ga];
                        Bhs[lane * 68 + r] = g_Bh[gb];
                    }
                    __syncthreads();
                    if (!is64) {
#pragma unroll
                        for (int half = 0; half < 2; half++) {
                            float acc[4][4] = {{0}};
#pragma unroll
                            for (int kk = 0; kk < 16; kk++) {
                                int k = half * 16 + kk;
                                float4 a4 = *(const float4*)(Ahs + k * 68 + tyr);
                                float4 b4 = *(const float4*)(Bhs + k * 68 + txc);
                                float av[4] = {a4.x, a4.y, a4.z, a4.w};
                                float bv[4] = {b4.x, b4.y, b4.z, b4.w};
#pragma unroll
                                for (int r = 0; r < 4; r++)
#pragma unroll
                                    for (int c = 0; c < 4; c++)
                                        acc[r][c] = __fmaf_rn(av[r], bv[c], acc[r][c]);
                            }
#pragma unroll
                            for (int r = 0; r < 4; r++)
#pragma unroll
                                for (int c = 0; c < 4; c++) {
                                    float ts = __fadd_rn(Sh_[r][c], acc[r][c]);
                                    float e  = __fadd_rn(__fsub_rn(Sh_[r][c], ts), acc[r][c]);
                                    Sh_[r][c] = ts;
                                    Sl_[r][c] = __fadd_rn(Sl_[r][c], e);
                                }
                        }
                    } else {
#pragma unroll
                        for (int half = 0; half < 2; half++) {
                            float acc[4][4] = {{0}};
                            float accl[4][4] = {{0}};
#pragma unroll
                            for (int kk = 0; kk < 16; kk++) {
                                int k = half * 16 + kk;
                                float4 a4 = *(const float4*)(Ahs + k * 68 + tyr);
                                float4 al4 = *(const float4*)(Als + k * 68 + tyr);
                                float4 b4 = *(const float4*)(Bhs + k * 68 + txc);
                                float av[4] = {a4.x, a4.y, a4.z, a4.w};
                                float alv[4] = {al4.x, al4.y, al4.z, al4.w};
                                float bv[4] = {b4.x, b4.y, b4.z, b4.w};
#pragma unroll
                                for (int r = 0; r < 4; r++)
#pragma unroll
                                    for (int c = 0; c < 4; c++) {
                                        acc[r][c]  = __fmaf_rn(av[r],  bv[c], acc[r][c]);
                                        accl[r][c] = __fmaf_rn(alv[r], bv[c], accl[r][c]);
                                    }
                            }
#pragma unroll
                            for (int r = 0; r < 4; r++)
#pragma unroll
                                for (int c = 0; c < 4; c++) {
                                    float ts = __fadd_rn(Sh_[r][c], acc[r][c]);
                                    float e  = __fadd_rn(__fsub_rn(Sh_[r][c], ts), acc[r][c]);
                                    Sh_[r][c] = ts;
                                    Sl_[r][c] = __fadd_rn(Sl_[r][c], __fadd_rn(e, accl[r][c]));
                                }
                        }
                    }
                    __syncthreads();
                }
#pragma unroll
                for (int r = 0; r < 4; r++)
#pragma unroll
                    for (int c = 0; c < 4; c++)
                        g_ADA[(size_t)(row0 + tyr + r) * NEQ + col0 + txc + c] =
                            (double)Sh_[r][c] + (double)Sl_[r][c];
            }
            // lookahead: block 0 owns Gram tile (0,0) -> factor panel 0 now
            if (bid == 0) {
                __syncthreads();
                potrf_panel(sh, 0, tid);
            }
        }
        gsync(tgt);

        // ---- Cholesky panels: [trsm || W-sweep] ; [syrk + potrf_{p+1}] ----
        for (int p = 0; p < 12; p++) {
            int o = p * 64, rem = NEQ - o - 64;

            // trsm data blocks (bid < rem/64); block 131 computes M_p = inv(L_pp)^T
            if ((rem > 0 && bid < rem / 64) || bid == NBLK - 1) {
                double* L = sh;          // [64][65]
                double* X = sh + 4160;   // [64][65]
                bool isW = (bid == NBLK - 1);
                int base = o + 64 + bid * 64;
                for (int i = tid; i < 4096; i += NTHR) {
                    int r = i >> 6, c = i & 63;
                    L[r * 65 + c] = g_ADA[(size_t)(o + r) * NEQ + o + c];
                    X[r * 65 + c] = isW ? ((r == c) ? 1.0 : 0.0)
                                        : g_ADA[(size_t)(base + r) * NEQ + o + c];
                }
                __syncthreads();   // REQUIRED before diag overwrite (cross-thread)
                if (tid < 64) L[tid * 65 + tid] = g_invd[o + tid];
                __syncthreads();
                int r = tid & 63, q = tid >> 6;
                for (int j = 0; j < 64; j++) {
                    if (q == 0) X[r * 65 + j] *= L[j * 65 + j];
                    __syncthreads();
                    double xj = X[r * 65 + j];
                    for (int c = j + 1 + q; c < 64; c += 4)
                        X[r * 65 + c] -= xj * L[c * 65 + j];
                    __syncthreads();
                }
                if (isW) {
                    for (int i = tid; i < 4096; i += NTHR) {
                        int rr = i >> 6, c = i & 63;
                        g_W[(size_t)p * 4096 + rr * 64 + c] = X[rr * 65 + c];
                    }
                } else {
                    for (int i = tid; i < 4096; i += NTHR) {
                        int rr = i >> 6, c = i & 63;
                        g_ADA[(size_t)(base + rr) * NEQ + o + c] = X[rr * 65 + c];
                    }
                }
            }
            gsync(tgt);

            // syrk: trailing C -= L21 L21^T; block 0 then factors panel p+1
            if (rem > 0) {
                int nb = rem / 64, nt = nb * (nb + 1) / 2;
                float* Ahs = (float*)sh;       // [32][68]
                float* Als = Ahs + 2176;
                float* Bhs = Als + 2176;
                float* Bls = Bhs + 2176;
                const int txc = (tid & 15) * 4;
                const int tyr = (tid >> 4) * 4;
                int o2 = o + 64;
                for (int t = bid; t < nt; t += NBLK) {
                    int bi, bj; tri_map(t, bi, bj);
                    int r0 = o2 + bi * 64, c0 = o2 + bj * 64;
                    float Hh[4][4] = {{0}}, Hl[4][4] = {{0}};
                    for (int kq = 0; kq < 64; kq += 32) {
                        for (int r = warp; r < 64; r += 8) {
                            double va = g_ADA[(size_t)(r0 + r) * NEQ + o + kq + lane];
                            double vb = g_ADA[(size_t)(c0 + r) * NEQ + o + kq + lane];
                            float ha = (float)va, hb = (float)vb;
                            Ahs[lane * 68 + r] = ha;
                            Als[lane * 68 + r] = (float)(va - (double)ha);
                            Bhs[lane * 68 + r] = hb;
                            Bls[lane * 68 + r] = (float)(vb - (double)hb);
                        }
                        __syncthreads();
#pragma unroll 4
                        for (int k = 0; k < 32; k++) {
                            float4 a4 = *(const float4*)(Ahs + k * 68 + tyr);
                            float4 al4 = *(const float4*)(Als + k * 68 + tyr);
                            float4 bh4 = *(const float4*)(Bhs + k * 68 + txc);
                            float4 bl4 = *(const float4*)(Bls + k * 68 + txc);
                            float av[4] = {a4.x, a4.y, a4.z, a4.w};
                            float alv[4] = {al4.x, al4.y, al4.z, al4.w};
                            float bh[4] = {bh4.x, bh4.y, bh4.z, bh4.w};
                            float bl[4] = {bl4.x, bl4.y, bl4.z, bl4.w};
#pragma unroll
                            for (int r = 0; r < 4; r++)
#pragma unroll
                                for (int c = 0; c < 4; c++) {
                                    float pf = __fmul_rn(av[r], bh[c]);
                                    float e = __fmaf_rn(av[r], bh[c], -pf);
                                    e = __fmaf_rn(av[r], bl[c], e);
                                    e = __fmaf_rn(alv[r], bh[c], e);
                                    float s = __fadd_rn(Hh[r][c], pf);
                                    float bb = __fsub_rn(s, Hh[r][c]);
                                    float err = __fadd_rn(__fsub_rn(Hh[r][c], __fsub_rn(s, bb)),
                                                          __fsub_rn(pf, bb));
                                    Hh[r][c] = s;
                                    Hl[r][c] = __fadd_rn(Hl[r][c], __fadd_rn(e, err));
                                }
                        }
                        __syncthreads();
                    }
#pragma unroll
                    for (int r = 0; r < 4; r++)
#pragma unroll
                        for (int c = 0; c < 4; c++)
                            g_ADA[(size_t)(r0 + tyr + r) * NEQ + c0 + txc + c] -=
                                ((double)Hh[r][c] + (double)Hl[r][c]);
                }
                // lookahead: block 0 just updated diagonal tile (o2,o2) -> factor panel p+1
                if (bid == 0) {
                    __syncthreads();
                    potrf_panel(sh, o2, tid);
                }
                gsync(tgt);
            }
        }

        // ---- triangular solves (block 0): diag via M_p matvecs + bulk updates ----
        if (bid == 0) {
            double* y   = sh;            // [768]
            double* Wm  = sh + 768;      // [64][65]
            double* tmp = sh + 4928;     // [4][64]
            for (int i = tid; i < NEQ; i += NTHR) y[i] = g_rhs[i];
            __syncthreads();
            int r = tid & 63, qg = tid >> 6;
            // forward: y_p = L_pp^{-1} y_p = M^T y_p ; then push to rows below
            for (int p = 0; p < 12; p++) {
                int o = p * 64;
                for (int i = tid; i < 4096; i += NTHR)
                    Wm[(i >> 6) * 65 + (i & 63)] = g_W[(size_t)p * 4096 + i];
                __syncthreads();
                double s = 0.0;
                for (int j = qg; j < 64; j += 4) s += Wm[j * 65 + r] * y[o + j];
                tmp[qg * 64 + r] = s;
                __syncthreads();
                if (tid < 64)
                    y[o + tid] = tmp[tid] + tmp[64 + tid] + tmp[128 + tid] + tmp[192 + tid];
                __syncthreads();
                for (int rr = o + 64 + warp; rr < NEQ; rr += 8) {
                    double s2 = 0.0;
#pragma unroll
                    for (int k = lane; k < 64; k += 32) s2 += g_ADA[(size_t)rr * NEQ + o + k] * y[o + k];
#pragma unroll
                    for (int off = 16; off; off >>= 1) s2 += __shfl_down_sync(0xffffffffu, s2, off);
                    if (lane == 0) y[rr] -= s2;
                }
                __syncthreads();
            }
            // backward: y_p = L_pp^{-T} y_p = M y_p ; then push to rows above
            for (int p = 11; p >= 0; p--) {
                int o = p * 64;
                for (int i = tid; i < 4096; i += NTHR)
                    Wm[(i >> 6) * 65 + (i & 63)] = g_W[(size_t)p * 4096 + i];
                __syncthreads();
                double s = 0.0;
                for (int j = qg; j < 64; j += 4) s += Wm[r * 65 + j] * y[o + j];
                tmp[qg * 64 + r] = s;
                __syncthreads();
                if (tid < 64)
                    y[o + tid] = tmp[tid] + tmp[64 + tid] + tmp[128 + tid] + tmp[192 + tid];
                __syncthreads();
                for (int i = tid; i < o; i += NTHR) {
                    double s2 = 0.0;
#pragma unroll 8
                    for (int jj = 0; jj < 64; jj++) s2 += g_ADA[(size_t)(o + jj) * NEQ + i] * y[o + jj];
                    y[i] -= s2;
                }
                __syncthreads();
            }
            for (int i = tid; i < NEQ; i += NTHR) g_dnu[i] = y[i];
        }
        gsync(tgt);

        atmv_phase(sh, 1, bid, tid, warp, lane);
        gsync(tgt);

        if (bid < 16) {
            int i = bid * NTHR + tid;
            double rt = g_rtil[i], t2 = g_t[i], Di = g_Dinv[i];
            double rc = g_rc[i], la = g_lam[i], zz = g_z[i];
            double dz = (rt - t2) * Di;
            double dl = (-rc - la * dz) / zz;
            g_dz[i] = dz; g_dlam[i] = dl;
            double mn = INFINITY;
            if (dz < 0.0) mn = fmin(mn, -zz / dz);
            if (dl < 0.0) mn = fmin(mn, -la / dl);
            blk_min_to(mn, s_red, tid, &s_val);
            if (tid == 0) g_pmin[bid] = s_val;
        }
        gsync(tgt);

        {
            double a = INFINITY;
#pragma unroll
            for (int j = 0; j < 16; j++) a = fmin(a, g_pmin[j]);
            a = fmin(1.0, 0.99 * a);
            if (bid < 16) {
                int i = bid * NTHR + tid;
                g_z[i]   += a * g_dz[i];
                g_lam[i] += a * g_dlam[i];
            } else if (bid < 19) {
                int i = (bid - 16) * NTHR + tid;
                if (i < NEQ) g_nu[i] += a * g_dnu[i];
            }
        }
        gsync(tgt);
    }

    if (bid < 16) {
        int i = bid * NTHR + tid;
        out[i] = (float)g_z[i];
    }
}

// ---------------- host launcher (2 graph nodes) ----------------
extern "C" void kernel_launch(void* const* d_in, const int* in_sizes, int n_in,
                              void* d_out, int out_size) {
    const float* puz  = (const float*)d_in[0];
    const void*  Araw = d_in[1];
    const float* logz = (const float*)d_in[2];
    float* out = (float*)d_out;

    static int attr_set = 0;
    if (!attr_set) {
        cudaFuncSetAttribute(k_main, cudaFuncAttributeMaxDynamicSharedMemorySize,
                             SMEM_DBL * (int)sizeof(double));
        attr_set = 1;
    }

    k_reset<<<1, 1>>>();
    k_main<<<NBLK, NTHR, SMEM_DBL * sizeof(double)>>>(puz, Araw, logz, out);
}